// round 10
// baseline (speedup 1.0000x reference)
#include <cuda_runtime.h>
#include <cstdint>

typedef unsigned long long ull;

#define B_  256
#define T_  250
#define C_  700
#define H1  1024
#define H2  512
#define O_  35
#define NB  148
#define THR 1.0f

// ---------------- device scratch (no allocations allowed) ----------------
__device__ float g_ff[(size_t)T_ * B_ * H1];      // [t][b][h1]
__device__ float g_W1T[C_ * H1];                  // [c][h1]
__device__ float g_WrecT[H1 * H1];                // [i][j]
__device__ float g_W2T[H1 * H2];                  // [i][j]
__device__ float g_v1[B_ * H1], g_a1[B_ * H1];
__device__ float g_s1[2][B_ * H1];                // ping-pong spikes layer1
__device__ float g_v2[B_ * H2], g_a2[B_ * H2];
__device__ float g_s2[2][B_ * H2];                // ping-pong spikes layer2
__device__ unsigned g_cnt, g_gen;                 // grid barrier state

// ---------------- f32x2 helpers ------------------------------------------
__device__ __forceinline__ ull pack2(float lo, float hi) {
    ull r; asm("mov.b64 %0, {%1, %2};" : "=l"(r) : "f"(lo), "f"(hi)); return r;
}
__device__ __forceinline__ void fma2(ull& d, ull a, ull b) {
    asm("fma.rn.f32x2 %0, %1, %2, %0;" : "+l"(d) : "l"(a), "l"(b));
}
__device__ __forceinline__ void unpack2(ull v, float& lo, float& hi) {
    asm("mov.b64 {%0, %1}, %2;" : "=f"(lo), "=f"(hi) : "l"(v));
}

// ---------------- software grid barrier (proven in R9) ---------------------
__device__ __forceinline__ void grid_sync(unsigned e) {
    __syncthreads();
    __threadfence();   // release
    if (threadIdx.x == 0) {
        unsigned prev = atomicAdd(&g_cnt, 1u);
        if (prev == NB - 1) {
            g_cnt = 0;
            __threadfence();
            atomicExch(&g_gen, e);
        } else {
            while (atomicAdd(&g_gen, 0u) < e) { __nanosleep(64); }
        }
    }
    __syncthreads();
    __threadfence();   // acquire (CCTL.IVALL -> no stale L1)
}

// ---------------- init ------------------------------------------------------
__global__ void init_kernel() {
    int i = blockIdx.x * blockDim.x + threadIdx.x;
    int stride = gridDim.x * blockDim.x;
    if (i == 0) { g_cnt = 0; g_gen = 0; }
    for (int k = i; k < B_ * H1; k += stride) {
        g_v1[k] = 0.f; g_a1[k] = 0.f; g_s1[0][k] = 0.f; g_s1[1][k] = 0.f;
    }
    for (int k = i; k < B_ * H2; k += stride) {
        g_v2[k] = 0.f; g_a2[k] = 0.f; g_s2[0][k] = 0.f; g_s2[1][k] = 0.f;
    }
}

// ---------------- transpose weights ----------------------------------------
__global__ void prep_kernel(const float* __restrict__ W1,
                            const float* __restrict__ Wrec,
                            const float* __restrict__ W2) {
    int i = blockIdx.x * blockDim.x + threadIdx.x;
    int stride = gridDim.x * blockDim.x;
    for (int k = i; k < C_ * H1; k += stride) {
        int c = k / H1, h = k % H1;
        g_W1T[k] = W1[h * C_ + c];
    }
    for (int k = i; k < H1 * H1; k += stride) {
        int r = k / H1, j = k % H1;
        g_WrecT[k] = Wrec[j * H1 + r];
    }
    for (int k = i; k < H1 * H2; k += stride) {
        int r = k / H2, j = k % H2;
        g_W2T[k] = W2[j * H1 + r];
    }
}

// ---------------- FF GEMM: 64x64 tile, 4x4/thread, dup-A, double-buffered ---
// g_ff[t*B+b][h] = x[b,t,:] . W1[h,:]   M=64000 N=1024 K=700 (chunks of 16)
#define FF_NC 44   // 44*16 = 704
__global__ void __launch_bounds__(256, 2) ff_kernel(const float* __restrict__ x) {
    __shared__ float Ad[2][16][132];   // dup-A: [k][2m(+pad)]
    __shared__ float Bsm[2][16][68];   // [k][n]
    const int tid = threadIdx.x;
    const int n0 = blockIdx.x * 64;
    const int row0 = blockIdx.y * 64;

    // load lanes
    const int lr = tid & 63;            // A row 0..63
    const int lk = (tid >> 6) << 2;     // A k offset 0,4,8,12
    const int bn = (tid & 15) << 2;     // B col
    const int bk = tid >> 4;            // B k row 0..15
    // compute lanes
    const int mb = (tid >> 4) << 2;     // 4 rows mb..mb+3
    const int nb = (tid & 15) << 2;     // 4 cols

    int grow = row0 + lr;
    int bb = grow & 255, tt = grow >> 8;
    const float* xr = &x[((size_t)bb * T_ + tt) * C_];

    ull acc[4][2];
#pragma unroll
    for (int m = 0; m < 4; ++m) { acc[m][0] = 0ull; acc[m][1] = 0ull; }

    // prologue: load + store chunk 0, load chunk 1
    float4 fa = make_float4(0.f,0.f,0.f,0.f);
    if (lk < C_) fa = *(const float4*)&xr[lk];
    float4 fb = make_float4(0.f,0.f,0.f,0.f);
    if (bk < C_) fb = *(const float4*)&g_W1T[(size_t)bk * H1 + n0 + bn];
    {
        *(ull*)&Ad[0][lk + 0][2*lr] = pack2(fa.x, fa.x);
        *(ull*)&Ad[0][lk + 1][2*lr] = pack2(fa.y, fa.y);
        *(ull*)&Ad[0][lk + 2][2*lr] = pack2(fa.z, fa.z);
        *(ull*)&Ad[0][lk + 3][2*lr] = pack2(fa.w, fa.w);
        *(float4*)&Bsm[0][bk][bn] = fb;
    }
    {
        int kc = 16;
        fa = make_float4(0.f,0.f,0.f,0.f);
        if (kc + lk < C_) fa = *(const float4*)&xr[kc + lk];
        fb = make_float4(0.f,0.f,0.f,0.f);
        if (kc + bk < C_) fb = *(const float4*)&g_W1T[(size_t)(kc + bk) * H1 + n0 + bn];
    }
    __syncthreads();

    for (int c = 0; c < FF_NC; ++c) {
        const int p = c & 1;
        if (c + 1 < FF_NC) {
            *(ull*)&Ad[1-p][lk + 0][2*lr] = pack2(fa.x, fa.x);
            *(ull*)&Ad[1-p][lk + 1][2*lr] = pack2(fa.y, fa.y);
            *(ull*)&Ad[1-p][lk + 2][2*lr] = pack2(fa.z, fa.z);
            *(ull*)&Ad[1-p][lk + 3][2*lr] = pack2(fa.w, fa.w);
            *(float4*)&Bsm[1-p][bk][bn] = fb;
            if (c + 2 < FF_NC) {
                int kc = (c + 2) * 16;
                fa = make_float4(0.f,0.f,0.f,0.f);
                if (kc + lk < C_) fa = *(const float4*)&xr[kc + lk];
                fb = make_float4(0.f,0.f,0.f,0.f);
                if (kc + bk < C_) fb = *(const float4*)&g_W1T[(size_t)(kc + bk) * H1 + n0 + bn];
            }
        }
        const float* Ab = &Ad[p][0][2*mb];
        const float* Bb = &Bsm[p][0][nb];
#pragma unroll
        for (int k = 0; k < 16; ++k) {
            float4 a01 = *(const float4*)(Ab + k*132);
            float4 a23 = *(const float4*)(Ab + k*132 + 4);
            float4 bf  = *(const float4*)(Bb + k*68);
            ull b0 = ((const ull*)&bf)[0], b1 = ((const ull*)&bf)[1];
            ull av0 = ((const ull*)&a01)[0], av1 = ((const ull*)&a01)[1];
            ull av2 = ((const ull*)&a23)[0], av3 = ((const ull*)&a23)[1];
            fma2(acc[0][0], av0, b0); fma2(acc[0][1], av0, b1);
            fma2(acc[1][0], av1, b0); fma2(acc[1][1], av1, b1);
            fma2(acc[2][0], av2, b0); fma2(acc[2][1], av2, b1);
            fma2(acc[3][0], av3, b0); fma2(acc[3][1], av3, b1);
        }
        __syncthreads();
    }
#pragma unroll
    for (int r = 0; r < 4; ++r) {
        size_t rbase = (size_t)(row0 + mb + r) * H1 + n0 + nb;
        float v0, v1, v2, v3;
        unpack2(acc[r][0], v0, v1);
        unpack2(acc[r][1], v2, v3);
        *(float4*)&g_ff[rbase] = make_float4(v0, v1, v2, v3);
    }
}

// ---------------- GEMM core for the step loop -------------------------------
// 32x64 tile, K=1024 (32 chunks of 32), 256 threads, 2x4/thread, dup-A,
// double-buffered, one __syncthreads per chunk.
__device__ __forceinline__ void gemm_core(
    const float* __restrict__ A, int lda,        // A[m][k]
    const float* __restrict__ Bm, int ldb,       // B[k][n]
    int m0, int n0, int tid,
    float (&sA)[2][32][68], float (&sB)[2][32][68],
    ull& a00, ull& a01, ull& a10, ull& a11)
{
    const int lr = tid & 31;            // A row
    const int lk = (tid >> 5) << 2;     // A k offset 0..28
    const int bn = (tid & 15) << 2;     // B col
    const int bk = tid >> 4;            // B k row (and +16)
    const int mb = (tid >> 4) << 1;     // compute rows mb, mb+1
    const int nb = (tid & 15) << 2;     // compute cols

    a00 = a01 = a10 = a11 = 0ull;

    const float* Arow  = A  + (size_t)(m0 + lr) * lda + lk;
    const float* Brow0 = Bm + (size_t)bk * ldb + n0 + bn;
    const float* Brow1 = Bm + (size_t)(bk + 16) * ldb + n0 + bn;

    // prologue: chunk 0 -> buf0, prefetch chunk 1
    float4 fa  = *(const float4*)Arow;
    float4 fb0 = *(const float4*)Brow0;
    float4 fb1 = *(const float4*)Brow1;
    *(ull*)&sA[0][lk + 0][2*lr] = pack2(fa.x, fa.x);
    *(ull*)&sA[0][lk + 1][2*lr] = pack2(fa.y, fa.y);
    *(ull*)&sA[0][lk + 2][2*lr] = pack2(fa.z, fa.z);
    *(ull*)&sA[0][lk + 3][2*lr] = pack2(fa.w, fa.w);
    *(float4*)&sB[0][bk][bn] = fb0;
    *(float4*)&sB[0][bk + 16][bn] = fb1;
    fa  = *(const float4*)(Arow + 32);
    fb0 = *(const float4*)(Brow0 + (size_t)32 * ldb);
    fb1 = *(const float4*)(Brow1 + (size_t)32 * ldb);
    __syncthreads();

    for (int c = 0; c < 32; ++c) {
        const int p = c & 1;
        if (c + 1 < 32) {
            *(ull*)&sA[1-p][lk + 0][2*lr] = pack2(fa.x, fa.x);
            *(ull*)&sA[1-p][lk + 1][2*lr] = pack2(fa.y, fa.y);
            *(ull*)&sA[1-p][lk + 2][2*lr] = pack2(fa.z, fa.z);
            *(ull*)&sA[1-p][lk + 3][2*lr] = pack2(fa.w, fa.w);
            *(float4*)&sB[1-p][bk][bn] = fb0;
            *(float4*)&sB[1-p][bk + 16][bn] = fb1;
            if (c + 2 < 32) {
                int ko = (c + 2) * 32;
                fa  = *(const float4*)(Arow + ko);
                fb0 = *(const float4*)(Brow0 + (size_t)ko * ldb);
                fb1 = *(const float4*)(Brow1 + (size_t)ko * ldb);
            }
        }
        const float* Ab = &sA[p][0][2*mb];
        const float* Bb = &sB[p][0][nb];
#pragma unroll
        for (int k = 0; k < 32; ++k) {
            float4 af = *(const float4*)(Ab + k*68);
            float4 bf = *(const float4*)(Bb + k*68);
            ull av0 = ((const ull*)&af)[0], av1 = ((const ull*)&af)[1];
            ull bv0 = ((const ull*)&bf)[0], bv1 = ((const ull*)&bf)[1];
            fma2(a00, av0, bv0); fma2(a01, av0, bv1);
            fma2(a10, av1, bv0); fma2(a11, av1, bv1);
        }
        __syncthreads();
    }
}

// ---------------- persistent SNN kernel ------------------------------------
// Per step:
//   P1: blocks 0..127 : GEMM1 32x64 (I1 = s1(t-1)@WrecT) + neuron1
//   barrier
//   P2: blocks 0..63  : GEMM2 32x64 (I2 = s1(t)@W2T) + neuron2
//       blocks 64..79 : readout(t-1) (vout/osum in registers)
//   barrier
__global__ void __launch_bounds__(256, 1) snn_kernel(
    const float* __restrict__ W3,
    const float* __restrict__ alpha1, const float* __restrict__ rho1,
    const float* __restrict__ ba1,
    const float* __restrict__ alpha2, const float* __restrict__ rho2,
    const float* __restrict__ ba2,
    const float* __restrict__ beta_out,
    float* __restrict__ out)
{
    __shared__ float sA[2][32][68];
    __shared__ float sB[2][32][68];
    const int tid = threadIdx.x;
    const int bx = blockIdx.x;
    unsigned epoch = 0;

    const int mb = (tid >> 4) << 1;
    const int nb = (tid & 15) << 2;

    // P1 tile (bx<128): m0a x n0a ; P2 tile (bx<64): m0b x n0b
    const int m0a = (bx >> 4) * 32, n0a = (bx & 15) * 64;
    const int m0b = (bx >> 3) * 32, n0b = (bx & 7) * 64;

    float4 al1, rh1, bb1, al2, rh2, bb2;
    if (bx < 128) {
        al1 = *(const float4*)&alpha1[n0a + nb];
        rh1 = *(const float4*)&rho1[n0a + nb];
        bb1 = *(const float4*)&ba1[n0a + nb];
    }
    if (bx < 64) {
        al2 = *(const float4*)&alpha2[n0b + nb];
        rh2 = *(const float4*)&rho2[n0b + nb];
        bb2 = *(const float4*)&ba2[n0b + nb];
    }
    // readout assignment (blocks 64..79)
    int rb[3], ro[3]; float rbo[3]; int nro = 0;
    float vo[3] = {0.f,0.f,0.f}, osum[3] = {0.f,0.f,0.f};
    if (bx >= 64 && bx < 80) {
        int base = (bx - 64) * 256 + tid;
        for (int jj = base; jj < B_ * O_; jj += 4096) {
            rb[nro] = jj / O_;
            ro[nro] = jj % O_;
            rbo[nro] = beta_out[jj % O_];
            nro++;
        }
    }

    for (int t = 0; t < T_; ++t) {
        const int par = t & 1;
        const float* __restrict__ s1r = g_s1[par];       // s1(t-1)
        float* __restrict__ s1w = g_s1[par ^ 1];         // s1(t)

        // =================== P1 ===================
        if (bx < 128) {
            ull a00, a01, a10, a11;
            gemm_core(s1r, H1, g_WrecT, H1, m0a, n0a, tid, sA, sB, a00, a01, a10, a11);

            const size_t ffb = (size_t)t * B_ * H1;
#pragma unroll
            for (int r = 0; r < 2; ++r) {
                size_t idx = (size_t)(m0a + mb + r) * H1 + n0a + nb;
                float i0, i1, i2, i3;
                unpack2(r ? a10 : a00, i0, i1);
                unpack2(r ? a11 : a01, i2, i3);
                float4 ffv = *(const float4*)&g_ff[ffb + idx];
                float4 spv = *(const float4*)&s1r[idx];
                float4 vv  = *(const float4*)&g_v1[idx];
                float4 aa  = *(const float4*)&g_a1[idx];
                float I0 = i0 + ffv.x, I1 = i1 + ffv.y, I2 = i2 + ffv.z, I3 = i3 + ffv.w;
                float vn0 = al1.x * (vv.x - spv.x * THR) + (1.f - al1.x) * (I0 - aa.x);
                float vn1 = al1.y * (vv.y - spv.y * THR) + (1.f - al1.y) * (I1 - aa.y);
                float vn2 = al1.z * (vv.z - spv.z * THR) + (1.f - al1.z) * (I2 - aa.z);
                float vn3 = al1.w * (vv.w - spv.w * THR) + (1.f - al1.w) * (I3 - aa.w);
                float s0  = (vn0 - THR >= 0.f) ? 1.f : 0.f;
                float s1f = (vn1 - THR >= 0.f) ? 1.f : 0.f;
                float s2f = (vn2 - THR >= 0.f) ? 1.f : 0.f;
                float s3  = (vn3 - THR >= 0.f) ? 1.f : 0.f;
                *(float4*)&g_v1[idx] = make_float4(vn0, vn1, vn2, vn3);
                *(float4*)&g_a1[idx] = make_float4(rh1.x * aa.x + bb1.x * s0,
                                                   rh1.y * aa.y + bb1.y * s1f,
                                                   rh1.z * aa.z + bb1.z * s2f,
                                                   rh1.w * aa.w + bb1.w * s3);
                *(float4*)&s1w[idx]  = make_float4(s0, s1f, s2f, s3);
            }
        }
        grid_sync(++epoch);

        // =================== P2 ===================
        if (bx < 64) {
            ull c00, c01, c10, c11;
            gemm_core(s1w, H1, g_W2T, H2, m0b, n0b, tid, sA, sB, c00, c01, c10, c11);

            const float* __restrict__ s2p = g_s2[par ^ 1];
            float* __restrict__ s2w = g_s2[par];
#pragma unroll
            for (int r = 0; r < 2; ++r) {
                size_t idx = (size_t)(m0b + mb + r) * H2 + n0b + nb;
                float i0, i1, i2, i3;
                unpack2(r ? c10 : c00, i0, i1);
                unpack2(r ? c11 : c01, i2, i3);
                float4 spv = *(const float4*)&s2p[idx];
                float4 vv  = *(const float4*)&g_v2[idx];
                float4 aa  = *(const float4*)&g_a2[idx];
                float vn0 = al2.x * (vv.x - spv.x * THR) + (1.f - al2.x) * (i0 - aa.x);
                float vn1 = al2.y * (vv.y - spv.y * THR) + (1.f - al2.y) * (i1 - aa.y);
                float vn2 = al2.z * (vv.z - spv.z * THR) + (1.f - al2.z) * (i2 - aa.z);
                float vn3 = al2.w * (vv.w - spv.w * THR) + (1.f - al2.w) * (i3 - aa.w);
                float s0  = (vn0 - THR >= 0.f) ? 1.f : 0.f;
                float s1f = (vn1 - THR >= 0.f) ? 1.f : 0.f;
                float s2f = (vn2 - THR >= 0.f) ? 1.f : 0.f;
                float s3  = (vn3 - THR >= 0.f) ? 1.f : 0.f;
                *(float4*)&g_v2[idx] = make_float4(vn0, vn1, vn2, vn3);
                *(float4*)&g_a2[idx] = make_float4(rh2.x * aa.x + bb2.x * s0,
                                                   rh2.y * aa.y + bb2.y * s1f,
                                                   rh2.z * aa.z + bb2.z * s2f,
                                                   rh2.w * aa.w + bb2.w * s3);
                *(float4*)&s2w[idx]  = make_float4(s0, s1f, s2f, s3);
            }
        } else if (bx < 80 && t > 0) {
            // readout for step t-1: s2(t-1) = g_s2[par^1]
            const float* __restrict__ s2r = g_s2[par ^ 1];
            for (int q = 0; q < nro; ++q) {
                const float4* sv = (const float4*)&s2r[rb[q] * H2];
                const float4* wv = (const float4*)&W3[ro[q] * H2];
                float4 acc4 = make_float4(0.f, 0.f, 0.f, 0.f);
#pragma unroll 4
                for (int k = 0; k < H2 / 4; ++k) {
                    float4 s4 = __ldcg(&sv[k]);
                    float4 w4 = __ldg(&wv[k]);
                    acc4.x += s4.x * w4.x; acc4.y += s4.y * w4.y;
                    acc4.z += s4.z * w4.z; acc4.w += s4.w * w4.w;
                }
                float I3 = (acc4.x + acc4.y) + (acc4.z + acc4.w);
                vo[q] = rbo[q] * vo[q] + (1.f - rbo[q]) * I3;
                osum[q] += vo[q];
            }
        }
        grid_sync(++epoch);
    }

    // ---- final readout for t = 249 + write output ----
    if (bx >= 64 && bx < 80) {
        const float* __restrict__ s2r = g_s2[(T_ - 1) & 1];
        for (int q = 0; q < nro; ++q) {
            const float4* sv = (const float4*)&s2r[rb[q] * H2];
            const float4* wv = (const float4*)&W3[ro[q] * H2];
            float4 acc4 = make_float4(0.f, 0.f, 0.f, 0.f);
#pragma unroll 4
            for (int k = 0; k < H2 / 4; ++k) {
                float4 s4 = __ldcg(&sv[k]);
                float4 w4 = __ldg(&wv[k]);
                acc4.x += s4.x * w4.x; acc4.y += s4.y * w4.y;
                acc4.z += s4.z * w4.z; acc4.w += s4.w * w4.w;
            }
            float I3 = (acc4.x + acc4.y) + (acc4.z + acc4.w);
            vo[q] = rbo[q] * vo[q] + (1.f - rbo[q]) * I3;
            osum[q] += vo[q];
            out[rb[q] * O_ + ro[q]] = osum[q] * (1.0f / (float)T_);
        }
    }
}

// ---------------- launch ---------------------------------------------------
extern "C" void kernel_launch(void* const* d_in, const int* in_sizes, int n_in,
                              void* d_out, int out_size) {
    const float* x      = (const float*)d_in[0];
    const float* W1     = (const float*)d_in[1];
    const float* Wrec   = (const float*)d_in[2];
    const float* W2     = (const float*)d_in[3];
    const float* W3     = (const float*)d_in[4];
    const float* alpha1 = (const float*)d_in[5];
    const float* rho1   = (const float*)d_in[6];
    const float* ba1    = (const float*)d_in[7];
    const float* alpha2 = (const float*)d_in[8];
    const float* rho2   = (const float*)d_in[9];
    const float* ba2    = (const float*)d_in[10];
    const float* bout   = (const float*)d_in[11];
    float* out = (float*)d_out;

    init_kernel<<<1024, 256>>>();
    prep_kernel<<<4096, 256>>>(W1, Wrec, W2);
    ff_kernel<<<dim3(16, 1000), 256>>>(x);
    snn_kernel<<<NB, 256>>>(W3, alpha1, rho1, ba1, alpha2, rho2, ba2, bout, out);
}

// round 12
// speedup vs baseline: 8.5119x; 8.5119x over previous
#include <cuda_runtime.h>
#include <cstdint>

typedef unsigned long long ull;

#define B_  256
#define T_  250
#define C_  700
#define H1  1024
#define H2  512
#define O_  35
#define NB  148
#define THR 1.0f

// ---------------- device scratch (no allocations allowed) ----------------
__device__ float g_ff[(size_t)T_ * B_ * H1];      // [t][b][h1]
__device__ float g_W1T[C_ * H1];                  // [c][h1]
__device__ float g_WrecT[H1 * H1];                // [i][j]
__device__ float g_W2T[H1 * H2];                  // [i][j]
__device__ float g_v1[B_ * H1], g_a1[B_ * H1];
__device__ float g_s1[2][B_ * H1];                // ping-pong spikes layer1
__device__ float g_v2[B_ * H2], g_a2[B_ * H2];
__device__ float g_s2[2][B_ * H2];                // ping-pong spikes layer2
__device__ unsigned g_cnt, g_gen;                 // grid barrier state
__device__ unsigned g_flag;                       // any layer-1 spike ever?

// ---------------- f32x2 helpers ------------------------------------------
__device__ __forceinline__ ull pack2(float lo, float hi) {
    ull r; asm("mov.b64 %0, {%1, %2};" : "=l"(r) : "f"(lo), "f"(hi)); return r;
}
__device__ __forceinline__ void fma2(ull& d, ull a, ull b) {
    asm("fma.rn.f32x2 %0, %1, %2, %0;" : "+l"(d) : "l"(a), "l"(b));
}
__device__ __forceinline__ void unpack2(ull v, float& lo, float& hi) {
    asm("mov.b64 {%0, %1}, %2;" : "=f"(lo), "=f"(hi) : "l"(v));
}

// ---------------- software grid barrier (proven R9) ------------------------
__device__ __forceinline__ void grid_sync(unsigned e) {
    __syncthreads();
    __threadfence();   // release
    if (threadIdx.x == 0) {
        unsigned prev = atomicAdd(&g_cnt, 1u);
        if (prev == NB - 1) {
            g_cnt = 0;
            __threadfence();
            atomicExch(&g_gen, e);
        } else {
            while (atomicAdd(&g_gen, 0u) < e) { __nanosleep(64); }
        }
    }
    __syncthreads();
    __threadfence();   // acquire
}

// ---------------- init ------------------------------------------------------
__global__ void init_kernel() {
    int i = blockIdx.x * blockDim.x + threadIdx.x;
    int stride = gridDim.x * blockDim.x;
    if (i == 0) { g_cnt = 0; g_gen = 0; g_flag = 0; }
    for (int k = i; k < B_ * H1; k += stride) {
        g_v1[k] = 0.f; g_a1[k] = 0.f; g_s1[0][k] = 0.f; g_s1[1][k] = 0.f;
    }
    for (int k = i; k < B_ * H2; k += stride) {
        g_v2[k] = 0.f; g_a2[k] = 0.f; g_s2[0][k] = 0.f; g_s2[1][k] = 0.f;
    }
}

// ---------------- transpose weights ----------------------------------------
__global__ void prep_kernel(const float* __restrict__ W1,
                            const float* __restrict__ Wrec,
                            const float* __restrict__ W2) {
    int i = blockIdx.x * blockDim.x + threadIdx.x;
    int stride = gridDim.x * blockDim.x;
    for (int k = i; k < C_ * H1; k += stride) {
        int c = k / H1, h = k % H1;
        g_W1T[k] = W1[h * C_ + c];
    }
    for (int k = i; k < H1 * H1; k += stride) {
        int r = k / H1, j = k % H1;
        g_WrecT[k] = Wrec[j * H1 + r];
    }
    for (int k = i; k < H1 * H2; k += stride) {
        int r = k / H2, j = k % H2;
        g_W2T[k] = W2[j * H1 + r];
    }
}

// ---------------- FF GEMM: 64x64 tile, 4x4/thread, dup-A, double-buffered ---
// g_ff[t*B+b][h] = x[b,t,:] . W1[h,:]   M=64000 N=1024 K=700 (chunks of 16)
#define FF_NC 44   // 44*16 = 704
__global__ void __launch_bounds__(256, 2) ff_kernel(const float* __restrict__ x) {
    __shared__ float Ad[2][16][132];   // dup-A: [k][2m(+pad)]
    __shared__ float Bsm[2][16][68];   // [k][n]
    const int tid = threadIdx.x;
    const int n0 = blockIdx.x * 64;
    const int row0 = blockIdx.y * 64;

    const int lr = tid & 63;            // A row 0..63
    const int lk = (tid >> 6) << 2;     // A k offset 0,4,8,12
    const int bn = (tid & 15) << 2;     // B col
    const int bk = tid >> 4;            // B k row 0..15
    const int mb = (tid >> 4) << 2;     // 4 rows mb..mb+3
    const int nb = (tid & 15) << 2;     // 4 cols

    int grow = row0 + lr;
    int bb = grow & 255, tt = grow >> 8;
    const float* xr = &x[((size_t)bb * T_ + tt) * C_];

    ull acc[4][2];
#pragma unroll
    for (int m = 0; m < 4; ++m) { acc[m][0] = 0ull; acc[m][1] = 0ull; }

    float4 fa = make_float4(0.f,0.f,0.f,0.f);
    if (lk < C_) fa = *(const float4*)&xr[lk];
    float4 fb = make_float4(0.f,0.f,0.f,0.f);
    if (bk < C_) fb = *(const float4*)&g_W1T[(size_t)bk * H1 + n0 + bn];
    {
        *(ull*)&Ad[0][lk + 0][2*lr] = pack2(fa.x, fa.x);
        *(ull*)&Ad[0][lk + 1][2*lr] = pack2(fa.y, fa.y);
        *(ull*)&Ad[0][lk + 2][2*lr] = pack2(fa.z, fa.z);
        *(ull*)&Ad[0][lk + 3][2*lr] = pack2(fa.w, fa.w);
        *(float4*)&Bsm[0][bk][bn] = fb;
    }
    {
        int kc = 16;
        fa = make_float4(0.f,0.f,0.f,0.f);
        if (kc + lk < C_) fa = *(const float4*)&xr[kc + lk];
        fb = make_float4(0.f,0.f,0.f,0.f);
        if (kc + bk < C_) fb = *(const float4*)&g_W1T[(size_t)(kc + bk) * H1 + n0 + bn];
    }
    __syncthreads();

    for (int c = 0; c < FF_NC; ++c) {
        const int p = c & 1;
        if (c + 1 < FF_NC) {
            *(ull*)&Ad[1-p][lk + 0][2*lr] = pack2(fa.x, fa.x);
            *(ull*)&Ad[1-p][lk + 1][2*lr] = pack2(fa.y, fa.y);
            *(ull*)&Ad[1-p][lk + 2][2*lr] = pack2(fa.z, fa.z);
            *(ull*)&Ad[1-p][lk + 3][2*lr] = pack2(fa.w, fa.w);
            *(float4*)&Bsm[1-p][bk][bn] = fb;
            if (c + 2 < FF_NC) {
                int kc = (c + 2) * 16;
                fa = make_float4(0.f,0.f,0.f,0.f);
                if (kc + lk < C_) fa = *(const float4*)&xr[kc + lk];
                fb = make_float4(0.f,0.f,0.f,0.f);
                if (kc + bk < C_) fb = *(const float4*)&g_W1T[(size_t)(kc + bk) * H1 + n0 + bn];
            }
        }
        const float* Ab = &Ad[p][0][2*mb];
        const float* Bb = &Bsm[p][0][nb];
#pragma unroll
        for (int k = 0; k < 16; ++k) {
            float4 a01 = *(const float4*)(Ab + k*132);
            float4 a23 = *(const float4*)(Ab + k*132 + 4);
            float4 bf  = *(const float4*)(Bb + k*68);
            ull b0 = ((const ull*)&bf)[0], b1 = ((const ull*)&bf)[1];
            ull av0 = ((const ull*)&a01)[0], av1 = ((const ull*)&a01)[1];
            ull av2 = ((const ull*)&a23)[0], av3 = ((const ull*)&a23)[1];
            fma2(acc[0][0], av0, b0); fma2(acc[0][1], av0, b1);
            fma2(acc[1][0], av1, b0); fma2(acc[1][1], av1, b1);
            fma2(acc[2][0], av2, b0); fma2(acc[2][1], av2, b1);
            fma2(acc[3][0], av3, b0); fma2(acc[3][1], av3, b1);
        }
        __syncthreads();
    }
#pragma unroll
    for (int r = 0; r < 4; ++r) {
        size_t rbase = (size_t)(row0 + mb + r) * H1 + n0 + nb;
        float v0, v1, v2, v3;
        unpack2(acc[r][0], v0, v1);
        unpack2(acc[r][1], v2, v3);
        *(float4*)&g_ff[rbase] = make_float4(v0, v1, v2, v3);
    }
}

// ---------------- sweep: per-(b,h) layer-1 dynamics, detect any spike -------
// Valid exactly while no spike has occurred anywhere (recurrent input == 0.0).
// If any element crosses threshold, set g_flag (dense fallback then recomputes
// everything from scratch, so over-detection is safe and under-detection
// impossible: the first spike in the true system is driven by ff alone).
__global__ void __launch_bounds__(256) sweep_kernel(
    const float* __restrict__ alpha1, const float* __restrict__ rho1,
    const float* __restrict__ ba1)
{
    int idx = blockIdx.x * blockDim.x + threadIdx.x;   // 0..B_*H1-1
    int h = idx & (H1 - 1);
    float al = alpha1[h], rh = rho1[h], bt = ba1[h];
    float v = 0.f, a = 0.f, s = 0.f;
    unsigned any = 0;
    const float* p = &g_ff[idx];
#pragma unroll 2
    for (int t = 0; t < T_; ++t) {
        float f = __ldcs(p);                       // streaming: no L2 pollution
        p += B_ * H1;
        float vn = al * (v - s * THR) + (1.f - al) * (f - a);
        s = (vn - THR >= 0.f) ? 1.f : 0.f;
        a = rh * a + bt * s;
        v = vn;
        any |= (s != 0.f);
    }
    if (any) atomicOr(&g_flag, 1u);
}

// ---------------- persistent SNN kernel (R9 fallback, flag-gated) -----------
__global__ void __launch_bounds__(256, 1) snn_kernel(
    const float* __restrict__ W3,
    const float* __restrict__ alpha1, const float* __restrict__ rho1,
    const float* __restrict__ ba1,
    const float* __restrict__ alpha2, const float* __restrict__ rho2,
    const float* __restrict__ ba2,
    const float* __restrict__ beta_out,
    float* __restrict__ out)
{
    const int tid = threadIdx.x;
    const int bx = blockIdx.x;

    // ---- fast path: no layer-1 spike ever => output is exactly zero ----
    if (g_flag == 0u) {
        for (int i = bx * 256 + tid; i < B_ * O_; i += NB * 256) out[i] = 0.f;
        return;
    }

    // ---- dense fallback (R9, proven) ----
    __shared__ float As[32][34];   // [k][m]
    __shared__ float Bs[32][68];   // [k][n]
    unsigned epoch = 0;

    const int m0  = (bx >> 4) * 32;
    const int n0  = (bx & 15) * 64;
    const int n0b = (bx & 15) * 32;
    const int la_m = tid >> 3;
    const int la_k = (tid & 7) << 2;
    const int lb_r = tid >> 4;
    const int lb_c = (tid & 15) << 2;
    const int mb   = (tid >> 4) << 1;
    const int nb   = (tid & 15) << 2;
    const int arow = tid >> 3;
    const int nb2  = (tid & 7) << 2;

    float4 al1, rh1, bb1, al2, rh2, bb2;
    if (bx < 128) {
        al1 = *(const float4*)&alpha1[n0 + nb];
        rh1 = *(const float4*)&rho1[n0 + nb];
        bb1 = *(const float4*)&ba1[n0 + nb];
        al2 = *(const float4*)&alpha2[n0b + nb2];
        rh2 = *(const float4*)&rho2[n0b + nb2];
        bb2 = *(const float4*)&ba2[n0b + nb2];
    }
    int rb[3], ro[3]; float rbo[3]; int nro = 0;
    float vo[3] = {0.f,0.f,0.f}, osum[3] = {0.f,0.f,0.f};
    if (bx >= 128 && bx < 144) {
        int base = (bx - 128) * 256 + tid;
        for (int jj = base; jj < B_ * O_; jj += 4096) {
            rb[nro] = jj / O_;
            ro[nro] = jj % O_;
            rbo[nro] = beta_out[jj % O_];
            nro++;
        }
    }

    for (int t = 0; t < T_; ++t) {
        const int par = t & 1;
        const float* __restrict__ s1r = g_s1[par];
        float* __restrict__ s1w = g_s1[par ^ 1];

        if (bx < 128) {
            ull a00 = 0, a01 = 0, a10 = 0, a11 = 0;
            float4 av  = __ldcg((const float4*)&s1r[(size_t)(m0 + la_m) * H1 + la_k]);
            float4 b0v = __ldg((const float4*)&g_WrecT[(size_t)lb_r * H1 + n0 + lb_c]);
            float4 b1v = __ldg((const float4*)&g_WrecT[(size_t)(lb_r + 16) * H1 + n0 + lb_c]);
            for (int k0 = 0; k0 < H1; k0 += 32) {
                __syncthreads();
                As[la_k + 0][la_m] = av.x;
                As[la_k + 1][la_m] = av.y;
                As[la_k + 2][la_m] = av.z;
                As[la_k + 3][la_m] = av.w;
                *(float4*)&Bs[lb_r][lb_c] = b0v;
                *(float4*)&Bs[lb_r + 16][lb_c] = b1v;
                __syncthreads();
                if (k0 + 32 < H1) {
                    int kn = k0 + 32;
                    av  = __ldcg((const float4*)&s1r[(size_t)(m0 + la_m) * H1 + kn + la_k]);
                    b0v = __ldg((const float4*)&g_WrecT[(size_t)(kn + lb_r) * H1 + n0 + lb_c]);
                    b1v = __ldg((const float4*)&g_WrecT[(size_t)(kn + lb_r + 16) * H1 + n0 + lb_c]);
                }
#pragma unroll
                for (int k = 0; k < 32; ++k) {
                    ull ap = *(const ull*)&As[k][mb];
                    float x0, x1; unpack2(ap, x0, x1);
                    ull bp0 = *(const ull*)&Bs[k][nb];
                    ull bp1 = *(const ull*)&Bs[k][nb + 2];
                    ull s0 = pack2(x0, x0), s1x = pack2(x1, x1);
                    fma2(a00, s0, bp0);  fma2(a01, s0, bp1);
                    fma2(a10, s1x, bp0); fma2(a11, s1x, bp1);
                }
            }
            const size_t ffb = (size_t)t * B_ * H1;
#pragma unroll
            for (int r = 0; r < 2; ++r) {
                int b = m0 + mb + r;
                size_t idx = (size_t)b * H1 + n0 + nb;
                float i0, i1, i2, i3;
                unpack2(r ? a10 : a00, i0, i1);
                unpack2(r ? a11 : a01, i2, i3);
                float4 ffv = __ldg((const float4*)&g_ff[ffb + idx]);
                float4 spv = *(const float4*)&s1r[idx];
                float4 vv  = *(const float4*)&g_v1[idx];
                float4 aa  = *(const float4*)&g_a1[idx];
                float I0 = i0 + ffv.x, I1 = i1 + ffv.y, I2 = i2 + ffv.z, I3 = i3 + ffv.w;
                float vn0 = al1.x * (vv.x - spv.x * THR) + (1.f - al1.x) * (I0 - aa.x);
                float vn1 = al1.y * (vv.y - spv.y * THR) + (1.f - al1.y) * (I1 - aa.y);
                float vn2 = al1.z * (vv.z - spv.z * THR) + (1.f - al1.z) * (I2 - aa.z);
                float vn3 = al1.w * (vv.w - spv.w * THR) + (1.f - al1.w) * (I3 - aa.w);
                float s0  = (vn0 - THR >= 0.f) ? 1.f : 0.f;
                float s1f = (vn1 - THR >= 0.f) ? 1.f : 0.f;
                float s2f = (vn2 - THR >= 0.f) ? 1.f : 0.f;
                float s3  = (vn3 - THR >= 0.f) ? 1.f : 0.f;
                *(float4*)&g_v1[idx] = make_float4(vn0, vn1, vn2, vn3);
                *(float4*)&g_a1[idx] = make_float4(rh1.x * aa.x + bb1.x * s0,
                                                   rh1.y * aa.y + bb1.y * s1f,
                                                   rh1.z * aa.z + bb1.z * s2f,
                                                   rh1.w * aa.w + bb1.w * s3);
                *(float4*)&s1w[idx]  = make_float4(s0, s1f, s2f, s3);
            }
        } else if (bx < 144 && t > 0) {
            const float* __restrict__ s2r = g_s2[par ^ 1];
            for (int q = 0; q < nro; ++q) {
                const float4* sv = (const float4*)&s2r[rb[q] * H2];
                const float4* wv = (const float4*)&W3[ro[q] * H2];
                float4 acc4 = make_float4(0.f, 0.f, 0.f, 0.f);
#pragma unroll 4
                for (int k = 0; k < H2 / 4; ++k) {
                    float4 s4 = __ldcg(&sv[k]);
                    float4 w4 = __ldg(&wv[k]);
                    acc4.x += s4.x * w4.x; acc4.y += s4.y * w4.y;
                    acc4.z += s4.z * w4.z; acc4.w += s4.w * w4.w;
                }
                float I3 = (acc4.x + acc4.y) + (acc4.z + acc4.w);
                vo[q] = rbo[q] * vo[q] + (1.f - rbo[q]) * I3;
                osum[q] += vo[q];
            }
        }
        grid_sync(++epoch);

        if (bx < 128) {
            const float* __restrict__ s1c = s1w;
            ull c0 = 0, c1 = 0;
            float4 av = __ldcg((const float4*)&s1c[(size_t)(m0 + la_m) * H1 + la_k]);
            float4 bv = __ldg((const float4*)&g_W2T[(size_t)arow * H2 + n0b + nb2]);
            for (int k0 = 0; k0 < H1; k0 += 32) {
                __syncthreads();
                As[la_k + 0][la_m] = av.x;
                As[la_k + 1][la_m] = av.y;
                As[la_k + 2][la_m] = av.z;
                As[la_k + 3][la_m] = av.w;
                *(float4*)&Bs[arow][nb2] = bv;
                __syncthreads();
                if (k0 + 32 < H1) {
                    int kn = k0 + 32;
                    av = __ldcg((const float4*)&s1c[(size_t)(m0 + la_m) * H1 + kn + la_k]);
                    bv = __ldg((const float4*)&g_W2T[(size_t)(kn + arow) * H2 + n0b + nb2]);
                }
#pragma unroll
                for (int k = 0; k < 32; ++k) {
                    float a = As[k][arow];
                    ull asp = pack2(a, a);
                    fma2(c0, asp, *(const ull*)&Bs[k][nb2]);
                    fma2(c1, asp, *(const ull*)&Bs[k][nb2 + 2]);
                }
            }
            int b = m0 + arow;
            size_t idx = (size_t)b * H2 + n0b + nb2;
            float i0, i1, i2, i3;
            unpack2(c0, i0, i1);
            unpack2(c1, i2, i3);
            const float* __restrict__ s2p = g_s2[par ^ 1];
            float* __restrict__ s2w = g_s2[par];
            float4 spv = *(const float4*)&s2p[idx];
            float4 vv  = *(const float4*)&g_v2[idx];
            float4 aa  = *(const float4*)&g_a2[idx];
            float vn0 = al2.x * (vv.x - spv.x * THR) + (1.f - al2.x) * (i0 - aa.x);
            float vn1 = al2.y * (vv.y - spv.y * THR) + (1.f - al2.y) * (i1 - aa.y);
            float vn2 = al2.z * (vv.z - spv.z * THR) + (1.f - al2.z) * (i2 - aa.z);
            float vn3 = al2.w * (vv.w - spv.w * THR) + (1.f - al2.w) * (i3 - aa.w);
            float s0  = (vn0 - THR >= 0.f) ? 1.f : 0.f;
            float s1f = (vn1 - THR >= 0.f) ? 1.f : 0.f;
            float s2f = (vn2 - THR >= 0.f) ? 1.f : 0.f;
            float s3  = (vn3 - THR >= 0.f) ? 1.f : 0.f;
            *(float4*)&g_v2[idx] = make_float4(vn0, vn1, vn2, vn3);
            *(float4*)&g_a2[idx] = make_float4(rh2.x * aa.x + bb2.x * s0,
                                               rh2.y * aa.y + bb2.y * s1f,
                                               rh2.z * aa.z + bb2.z * s2f,
                                               rh2.w * aa.w + bb2.w * s3);
            *(float4*)&s2w[idx]  = make_float4(s0, s1f, s2f, s3);
        }
        grid_sync(++epoch);
    }

    if (bx >= 128 && bx < 144) {
        const float* __restrict__ s2r = g_s2[(T_ - 1) & 1];
        for (int q = 0; q < nro; ++q) {
            const float4* sv = (const float4*)&s2r[rb[q] * H2];
            const float4* wv = (const float4*)&W3[ro[q] * H2];
            float4 acc4 = make_float4(0.f, 0.f, 0.f, 0.f);
#pragma unroll 4
            for (int k = 0; k < H2 / 4; ++k) {
                float4 s4 = __ldcg(&sv[k]);
                float4 w4 = __ldg(&wv[k]);
                acc4.x += s4.x * w4.x; acc4.y += s4.y * w4.y;
                acc4.z += s4.z * w4.z; acc4.w += s4.w * w4.w;
            }
            float I3 = (acc4.x + acc4.y) + (acc4.z + acc4.w);
            vo[q] = rbo[q] * vo[q] + (1.f - rbo[q]) * I3;
            osum[q] += vo[q];
            out[rb[q] * O_ + ro[q]] = osum[q] * (1.0f / (float)T_);
        }
    }
}

// ---------------- launch ---------------------------------------------------
extern "C" void kernel_launch(void* const* d_in, const int* in_sizes, int n_in,
                              void* d_out, int out_size) {
    const float* x      = (const float*)d_in[0];
    const float* W1     = (const float*)d_in[1];
    const float* Wrec   = (const float*)d_in[2];
    const float* W2     = (const float*)d_in[3];
    const float* W3     = (const float*)d_in[4];
    const float* alpha1 = (const float*)d_in[5];
    const float* rho1   = (const float*)d_in[6];
    const float* ba1    = (const float*)d_in[7];
    const float* alpha2 = (const float*)d_in[8];
    const float* rho2   = (const float*)d_in[9];
    const float* ba2    = (const float*)d_in[10];
    const float* bout   = (const float*)d_in[11];
    float* out = (float*)d_out;

    init_kernel<<<1024, 256>>>();
    prep_kernel<<<4096, 256>>>(W1, Wrec, W2);
    ff_kernel<<<dim3(16, 1000), 256>>>(x);
    sweep_kernel<<<B_ * H1 / 256, 256>>>(alpha1, rho1, ba1);
    snn_kernel<<<NB, 256>>>(W3, alpha1, rho1, ba1, alpha2, rho2, ba2, bout, out);
}

// round 15
// speedup vs baseline: 41.4224x; 4.8664x over previous
#include <cuda_runtime.h>
#include <cuda_bf16.h>
#include <cstdint>

typedef unsigned long long ull;

#define B_  256
#define T_  250
#define C_  700
#define KP  704
#define H1  1024
#define H2  512
#define O_  35
#define NB  148
#define THR 1.0f
#define MROWS (T_ * B_)      // 64000
#define NCH 11               // 704 / 64 k-chunks

// ---------------- device scratch (no allocations allowed) ----------------
__device__ float g_ff[(size_t)T_ * B_ * H1];           // [t][b][h1]  262MB
__device__ __nv_bfloat16 g_xbf[(size_t)MROWS * KP];    // [row][k]    90MB
__device__ __nv_bfloat16 g_w1bf[(size_t)H1 * KP];      // [h][k]      1.4MB
__device__ float g_WrecT[H1 * H1];
__device__ float g_W2T[H1 * H2];
__device__ float g_v1[B_ * H1], g_a1[B_ * H1];
__device__ float g_s1[2][B_ * H1];
__device__ float g_v2[B_ * H2], g_a2[B_ * H2];
__device__ float g_s2[2][B_ * H2];
__device__ unsigned g_cnt, g_gen;
__device__ unsigned g_flag;

// ---------------- f32x2 helpers (fallback path) ----------------------------
__device__ __forceinline__ ull pack2(float lo, float hi) {
    ull r; asm("mov.b64 %0, {%1, %2};" : "=l"(r) : "f"(lo), "f"(hi)); return r;
}
__device__ __forceinline__ void fma2(ull& d, ull a, ull b) {
    asm("fma.rn.f32x2 %0, %1, %2, %0;" : "+l"(d) : "l"(a), "l"(b));
}
__device__ __forceinline__ void unpack2(ull v, float& lo, float& hi) {
    asm("mov.b64 {%0, %1}, %2;" : "=f"(lo), "=f"(hi) : "l"(v));
}

__device__ __forceinline__ uint32_t smem_u32(const void* p) {
    uint32_t a;
    asm("{ .reg .u64 t; cvta.to.shared.u64 t, %1; cvt.u32.u64 %0, t; }"
        : "=r"(a) : "l"(p));
    return a;
}

// ---------------- software grid barrier (proven R9) ------------------------
__device__ __forceinline__ void grid_sync(unsigned e) {
    __syncthreads();
    __threadfence();
    if (threadIdx.x == 0) {
        unsigned prev = atomicAdd(&g_cnt, 1u);
        if (prev == NB - 1) {
            g_cnt = 0;
            __threadfence();
            atomicExch(&g_gen, e);
        } else {
            while (atomicAdd(&g_gen, 0u) < e) { __nanosleep(64); }
        }
    }
    __syncthreads();
    __threadfence();
}

// ---------------- init ------------------------------------------------------
__global__ void init_kernel() {
    int i = blockIdx.x * blockDim.x + threadIdx.x;
    int stride = gridDim.x * blockDim.x;
    if (i == 0) { g_cnt = 0; g_gen = 0; g_flag = 0; }
    for (int k = i; k < B_ * H1; k += stride) {
        g_v1[k] = 0.f; g_a1[k] = 0.f; g_s1[0][k] = 0.f; g_s1[1][k] = 0.f;
    }
    for (int k = i; k < B_ * H2; k += stride) {
        g_v2[k] = 0.f; g_a2[k] = 0.f; g_s2[0][k] = 0.f; g_s2[1][k] = 0.f;
    }
}

// ---------------- transpose weights (fallback path only) --------------------
__global__ void prep_kernel(const float* __restrict__ Wrec,
                            const float* __restrict__ W2) {
    int i = blockIdx.x * blockDim.x + threadIdx.x;
    int stride = gridDim.x * blockDim.x;
    for (int k = i; k < H1 * H1; k += stride) {
        int r = k / H1, j = k % H1;
        g_WrecT[k] = Wrec[j * H1 + r];
    }
    for (int k = i; k < H1 * H2; k += stride) {
        int r = k / H2, j = k % H2;
        g_W2T[k] = W2[j * H1 + r];
    }
}

// ---------------- convert x, W1 to bf16 (K padded to 704) -------------------
__global__ void __launch_bounds__(256) convert_kernel(
    const float* __restrict__ x, const float* __restrict__ W1) {
    size_t i = (size_t)blockIdx.x * blockDim.x + threadIdx.x;
    size_t stride = (size_t)gridDim.x * blockDim.x;
    const size_t NX = (size_t)MROWS * KP;
    for (size_t k = i; k < NX; k += stride) {
        int row = (int)(k / KP), c = (int)(k % KP);
        int b = row & 255, t = row >> 8;
        float v = (c < C_) ? x[((size_t)b * T_ + t) * C_ + c] : 0.f;
        g_xbf[k] = __float2bfloat16(v);
    }
    const size_t NW = (size_t)H1 * KP;
    for (size_t k = i; k < NW; k += stride) {
        int h = (int)(k / KP), c = (int)(k % KP);
        float v = (c < C_) ? W1[(size_t)h * C_ + c] : 0.f;
        g_w1bf[k] = __float2bfloat16(v);
    }
}

// ---------------- FF GEMM via mma.sync bf16 (HMMA, sm_103-safe) -------------
// g_ff[row][h] = sum_k xbf[row][k] * w1bf[h][k]
// CTA tile 128x128, K chunks of 64 bf16 (128B/row, SW128 swizzle),
// cp.async double-buffered, 8 warps (2M x 4N), warp tile 64x32.
__global__ void __launch_bounds__(256) ff_mma_kernel() {
    extern __shared__ __align__(1024) char dsm[];
    const int tid = threadIdx.x;
    const int wid = tid >> 5, lane = tid & 31;
    const int n0 = blockIdx.x * 128;
    const int row0 = blockIdx.y * 128;

    const uint32_t smem0 = smem_u32(dsm);
    // buffers: A0,A1,B0,B1 each 16KB
    const uint32_t sAb[2] = { smem0, smem0 + 16384 };
    const uint32_t sBb[2] = { smem0 + 32768, smem0 + 49152 };

    // ---- load mapping: thread -> (row r, half q), 64B each for A and B ----
    const int r = tid & 127;
    const int q = tid >> 7;                 // 0..1
    const char* gA = (const char*)g_xbf + (size_t)(row0 + r) * (KP * 2) + q * 64;
    const char* gB = (const char*)g_w1bf + (size_t)(n0 + r) * (KP * 2) + q * 64;
    const uint32_t xorv_r = (r & 7) << 4;   // SW128 xor for this row
    uint32_t sAoff[4], sBoff[4];
#pragma unroll
    for (int o = 0; o < 4; ++o) {
        uint32_t kb = q * 64 + o * 16;
        sAoff[o] = r * 128 + (kb ^ xorv_r);
        sBoff[o] = sAoff[o];
    }

    // ---- compute mapping ----
    const int wm = wid & 1;                 // M half (64)
    const int wn = wid >> 1;                // N quarter (32)
    float acc[4][4][4];
#pragma unroll
    for (int a = 0; a < 4; ++a)
#pragma unroll
        for (int b = 0; b < 4; ++b)
#pragma unroll
            for (int c = 0; c < 4; ++c) acc[a][b][c] = 0.f;

    // per-lane ldmatrix row indices (fixed across ksteps)
    int a_row[4], b_row[2];
#pragma unroll
    for (int mi = 0; mi < 4; ++mi)
        a_row[mi] = wm * 64 + mi * 16 + (lane & 15);
#pragma unroll
    for (int pj = 0; pj < 2; ++pj)
        b_row[pj] = wn * 32 + pj * 16 + ((lane >> 4) & 1) * 8 + (lane & 7);
    const uint32_t a_klane = ((lane >> 4) & 1) * 16;   // A k half (16B)
    const uint32_t b_klane = ((lane >> 3) & 1) * 16;   // B k half (16B)

#define ISSUE(ch, buf) do {                                                      \
        const char* ga_ = gA + (ch) * 128;                                       \
        const char* gb_ = gB + (ch) * 128;                                       \
        _Pragma("unroll")                                                        \
        for (int o = 0; o < 4; ++o) {                                            \
            asm volatile("cp.async.cg.shared.global [%0], [%1], 16;"             \
                         :: "r"(sAb[buf] + sAoff[o]), "l"(ga_ + o * 16));        \
            asm volatile("cp.async.cg.shared.global [%0], [%1], 16;"             \
                         :: "r"(sBb[buf] + sBoff[o]), "l"(gb_ + o * 16));        \
        }                                                                        \
        asm volatile("cp.async.commit_group;" ::: "memory");                     \
    } while (0)

    ISSUE(0, 0);

    for (int ch = 0; ch < NCH; ++ch) {
        const int p = ch & 1;
        asm volatile("cp.async.wait_group 0;" ::: "memory");
        __syncthreads();
        if (ch + 1 < NCH) ISSUE(ch + 1, 1 - p);

#pragma unroll
        for (int ks = 0; ks < 4; ++ks) {
            const uint32_t kbase = ks * 32;
            uint32_t a[4][4], bf[4][2];
#pragma unroll
            for (int mi = 0; mi < 4; ++mi) {
                uint32_t addr = sAb[p] + a_row[mi] * 128 +
                                ((kbase + a_klane) ^ ((a_row[mi] & 7) << 4));
                asm volatile(
                    "ldmatrix.sync.aligned.m8n8.x4.shared.b16 {%0,%1,%2,%3}, [%4];"
                    : "=r"(a[mi][0]), "=r"(a[mi][1]), "=r"(a[mi][2]), "=r"(a[mi][3])
                    : "r"(addr));
            }
#pragma unroll
            for (int pj = 0; pj < 2; ++pj) {
                uint32_t addr = sBb[p] + b_row[pj] * 128 +
                                ((kbase + b_klane) ^ ((b_row[pj] & 7) << 4));
                uint32_t r0, r1, r2, r3;
                asm volatile(
                    "ldmatrix.sync.aligned.m8n8.x4.shared.b16 {%0,%1,%2,%3}, [%4];"
                    : "=r"(r0), "=r"(r1), "=r"(r2), "=r"(r3)
                    : "r"(addr));
                bf[pj * 2 + 0][0] = r0; bf[pj * 2 + 0][1] = r1;
                bf[pj * 2 + 1][0] = r2; bf[pj * 2 + 1][1] = r3;
            }
#pragma unroll
            for (int mi = 0; mi < 4; ++mi) {
#pragma unroll
                for (int nj = 0; nj < 4; ++nj) {
                    asm volatile(
                        "mma.sync.aligned.m16n8k16.row.col.f32.bf16.bf16.f32 "
                        "{%0,%1,%2,%3}, {%4,%5,%6,%7}, {%8,%9}, {%0,%1,%2,%3};"
                        : "+f"(acc[mi][nj][0]), "+f"(acc[mi][nj][1]),
                          "+f"(acc[mi][nj][2]), "+f"(acc[mi][nj][3])
                        : "r"(a[mi][0]), "r"(a[mi][1]), "r"(a[mi][2]), "r"(a[mi][3]),
                          "r"(bf[nj][0]), "r"(bf[nj][1]));
                }
            }
        }
        __syncthreads();
    }

    // ---- epilogue: C fragment -> g_ff[row][h], float2 stores ----
    const int g = lane >> 2, tig = lane & 3;
#pragma unroll
    for (int mi = 0; mi < 4; ++mi) {
        int baseRow = row0 + wm * 64 + mi * 16;
#pragma unroll
        for (int nj = 0; nj < 4; ++nj) {
            int col = n0 + wn * 32 + nj * 8 + tig * 2;
            float2 lo = make_float2(acc[mi][nj][0], acc[mi][nj][1]);
            float2 hi = make_float2(acc[mi][nj][2], acc[mi][nj][3]);
            *(float2*)&g_ff[(size_t)(baseRow + g) * H1 + col] = lo;
            *(float2*)&g_ff[(size_t)(baseRow + g + 8) * H1 + col] = hi;
        }
    }
#undef ISSUE
}

// ---------------- sweep: per-(b,h) layer-1 dynamics, detect any spike -------
__global__ void __launch_bounds__(256) sweep_kernel(
    const float* __restrict__ alpha1, const float* __restrict__ rho1,
    const float* __restrict__ ba1)
{
    int idx = blockIdx.x * blockDim.x + threadIdx.x;   // 0..B_*H1-1
    int h = idx & (H1 - 1);
    float al = alpha1[h], rh = rho1[h], bt = ba1[h];
    float v = 0.f, a = 0.f, s = 0.f;
    unsigned any = 0;
    const float* p = &g_ff[idx];
#pragma unroll 2
    for (int t = 0; t < T_; ++t) {
        float f = __ldcs(p);
        p += B_ * H1;
        float vn = al * (v - s * THR) + (1.f - al) * (f - a);
        s = (vn - THR >= 0.f) ? 1.f : 0.f;
        a = rh * a + bt * s;
        v = vn;
        any |= (s != 0.f);
    }
    if (any) atomicOr(&g_flag, 1u);
}

// ---------------- persistent SNN kernel (flag-gated fallback, R12) ----------
__global__ void __launch_bounds__(256, 1) snn_kernel(
    const float* __restrict__ W3,
    const float* __restrict__ alpha1, const float* __restrict__ rho1,
    const float* __restrict__ ba1,
    const float* __restrict__ alpha2, const float* __restrict__ rho2,
    const float* __restrict__ ba2,
    const float* __restrict__ beta_out,
    float* __restrict__ out)
{
    const int tid = threadIdx.x;
    const int bx = blockIdx.x;

    if (g_flag == 0u) {
        for (int i = bx * 256 + tid; i < B_ * O_; i += NB * 256) out[i] = 0.f;
        return;
    }

    __shared__ float As[32][34];
    __shared__ float Bs[32][68];
    unsigned epoch = 0;

    const int m0  = (bx >> 4) * 32;
    const int n0  = (bx & 15) * 64;
    const int n0b = (bx & 15) * 32;
    const int la_m = tid >> 3;
    const int la_k = (tid & 7) << 2;
    const int lb_r = tid >> 4;
    const int lb_c = (tid & 15) << 2;
    const int mb   = (tid >> 4) << 1;
    const int nb   = (tid & 15) << 2;
    const int arow = tid >> 3;
    const int nb2  = (tid & 7) << 2;

    float4 al1, rh1, bb1, al2, rh2, bb2;
    if (bx < 128) {
        al1 = *(const float4*)&alpha1[n0 + nb];
        rh1 = *(const float4*)&rho1[n0 + nb];
        bb1 = *(const float4*)&ba1[n0 + nb];
        al2 = *(const float4*)&alpha2[n0b + nb2];
        rh2 = *(const float4*)&rho2[n0b + nb2];
        bb2 = *(const float4*)&ba2[n0b + nb2];
    }
    int rb[3], ro[3]; float rbo[3]; int nro = 0;
    float vo[3] = {0.f,0.f,0.f}, osum[3] = {0.f,0.f,0.f};
    if (bx >= 128 && bx < 144) {
        int base = (bx - 128) * 256 + tid;
        for (int jj = base; jj < B_ * O_; jj += 4096) {
            rb[nro] = jj / O_;
            ro[nro] = jj % O_;
            rbo[nro] = beta_out[jj % O_];
            nro++;
        }
    }

    for (int t = 0; t < T_; ++t) {
        const int par = t & 1;
        const float* __restrict__ s1r = g_s1[par];
        float* __restrict__ s1w = g_s1[par ^ 1];

        if (bx < 128) {
            ull a00 = 0, a01 = 0, a10 = 0, a11 = 0;
            float4 av  = __ldcg((const float4*)&s1r[(size_t)(m0 + la_m) * H1 + la_k]);
            float4 b0v = __ldg((const float4*)&g_WrecT[(size_t)lb_r * H1 + n0 + lb_c]);
            float4 b1v = __ldg((const float4*)&g_WrecT[(size_t)(lb_r + 16) * H1 + n0 + lb_c]);
            for (int k0 = 0; k0 < H1; k0 += 32) {
                __syncthreads();
                As[la_k + 0][la_m] = av.x;
                As[la_k + 1][la_m] = av.y;
                As[la_k + 2][la_m] = av.z;
                As[la_k + 3][la_m] = av.w;
                *(float4*)&Bs[lb_r][lb_c] = b0v;
                *(float4*)&Bs[lb_r + 16][lb_c] = b1v;
                __syncthreads();
                if (k0 + 32 < H1) {
                    int kn = k0 + 32;
                    av  = __ldcg((const float4*)&s1r[(size_t)(m0 + la_m) * H1 + kn + la_k]);
                    b0v = __ldg((const float4*)&g_WrecT[(size_t)(kn + lb_r) * H1 + n0 + lb_c]);
                    b1v = __ldg((const float4*)&g_WrecT[(size_t)(kn + lb_r + 16) * H1 + n0 + lb_c]);
                }
#pragma unroll
                for (int k = 0; k < 32; ++k) {
                    ull ap = *(const ull*)&As[k][mb];
                    float x0, x1; unpack2(ap, x0, x1);
                    ull bp0 = *(const ull*)&Bs[k][nb];
                    ull bp1 = *(const ull*)&Bs[k][nb + 2];
                    ull s0 = pack2(x0, x0), s1x = pack2(x1, x1);
                    fma2(a00, s0, bp0);  fma2(a01, s0, bp1);
                    fma2(a10, s1x, bp0); fma2(a11, s1x, bp1);
                }
            }
            const size_t ffb = (size_t)t * B_ * H1;
#pragma unroll
            for (int r = 0; r < 2; ++r) {
                int b = m0 + mb + r;
                size_t idx = (size_t)b * H1 + n0 + nb;
                float i0, i1, i2, i3;
                unpack2(r ? a10 : a00, i0, i1);
                unpack2(r ? a11 : a01, i2, i3);
                float4 ffv = __ldg((const float4*)&g_ff[ffb + idx]);
                float4 spv = *(const float4*)&s1r[idx];
                float4 vv  = *(const float4*)&g_v1[idx];
                float4 aa  = *(const float4*)&g_a1[idx];
                float I0 = i0 + ffv.x, I1 = i1 + ffv.y, I2 = i2 + ffv.z, I3 = i3 + ffv.w;
                float vn0 = al1.x * (vv.x - spv.x * THR) + (1.f - al1.x) * (I0 - aa.x);
                float vn1 = al1.y * (vv.y - spv.y * THR) + (1.f - al1.y) * (I1 - aa.y);
                float vn2 = al1.z * (vv.z - spv.z * THR) + (1.f - al1.z) * (I2 - aa.z);
                float vn3 = al1.w * (vv.w - spv.w * THR) + (1.f - al1.w) * (I3 - aa.w);
                float s0  = (vn0 - THR >= 0.f) ? 1.f : 0.f;
                float s1f = (vn1 - THR >= 0.f) ? 1.f : 0.f;
                float s2f = (vn2 - THR >= 0.f) ? 1.f : 0.f;
                float s3  = (vn3 - THR >= 0.f) ? 1.f : 0.f;
                *(float4*)&g_v1[idx] = make_float4(vn0, vn1, vn2, vn3);
                *(float4*)&g_a1[idx] = make_float4(rh1.x * aa.x + bb1.x * s0,
                                                   rh1.y * aa.y + bb1.y * s1f,
                                                   rh1.z * aa.z + bb1.z * s2f,
                                                   rh1.w * aa.w + bb1.w * s3);
                *(float4*)&s1w[idx]  = make_float4(s0, s1f, s2f, s3);
            }
        } else if (bx < 144 && t > 0) {
            const float* __restrict__ s2r = g_s2[par ^ 1];
            for (int q = 0; q < nro; ++q) {
                const float4* sv = (const float4*)&s2r[rb[q] * H2];
                const float4* wv = (const float4*)&W3[ro[q] * H2];
                float4 acc4 = make_float4(0.f, 0.f, 0.f, 0.f);
#pragma unroll 4
                for (int k = 0; k < H2 / 4; ++k) {
                    float4 s4 = __ldcg(&sv[k]);
                    float4 w4 = __ldg(&wv[k]);
                    acc4.x += s4.x * w4.x; acc4.y += s4.y * w4.y;
                    acc4.z += s4.z * w4.z; acc4.w += s4.w * w4.w;
                }
                float I3 = (acc4.x + acc4.y) + (acc4.z + acc4.w);
                vo[q] = rbo[q] * vo[q] + (1.f - rbo[q]) * I3;
                osum[q] += vo[q];
            }
        }
        grid_sync(++epoch);

        if (bx < 128) {
            const float* __restrict__ s1c = s1w;
            ull c0 = 0, c1 = 0;
            float4 av = __ldcg((const float4*)&s1c[(size_t)(m0 + la_m) * H1 + la_k]);
            float4 bv = __ldg((const float4*)&g_W2T[(size_t)arow * H2 + n0b + nb2]);
            for (int k0 = 0; k0 < H1; k0 += 32) {
                __syncthreads();
                As[la_k + 0][la_m] = av.x;
                As[la_k + 1][la_m] = av.y;
                As[la_k + 2][la_m] = av.z;
                As[la_k + 3][la_m] = av.w;
                *(float4*)&Bs[arow][nb2] = bv;
                __syncthreads();
                if (k0 + 32 < H1) {
                    int kn = k0 + 32;
                    av = __ldcg((const float4*)&s1c[(size_t)(m0 + la_m) * H1 + kn + la_k]);
                    bv = __ldg((const float4*)&g_W2T[(size_t)(kn + arow) * H2 + n0b + nb2]);
                }
#pragma unroll
                for (int k = 0; k < 32; ++k) {
                    float a = As[k][arow];
                    ull asp = pack2(a, a);
                    fma2(c0, asp, *(const ull*)&Bs[k][nb2]);
                    fma2(c1, asp, *(const ull*)&Bs[k][nb2 + 2]);
                }
            }
            int b = m0 + arow;
            size_t idx = (size_t)b * H2 + n0b + nb2;
            float i0, i1, i2, i3;
            unpack2(c0, i0, i1);
            unpack2(c1, i2, i3);
            const float* __restrict__ s2p = g_s2[par ^ 1];
            float* __restrict__ s2w = g_s2[par];
            float4 spv = *(const float4*)&s2p[idx];
            float4 vv  = *(const float4*)&g_v2[idx];
            float4 aa  = *(const float4*)&g_a2[idx];
            float vn0 = al2.x * (vv.x - spv.x * THR) + (1.f - al2.x) * (i0 - aa.x);
            float vn1 = al2.y * (vv.y - spv.y * THR) + (1.f - al2.y) * (i1 - aa.y);
            float vn2 = al2.z * (vv.z - spv.z * THR) + (1.f - al2.z) * (i2 - aa.z);
            float vn3 = al2.w * (vv.w - spv.w * THR) + (1.f - al2.w) * (i3 - aa.w);
            float s0  = (vn0 - THR >= 0.f) ? 1.f : 0.f;
            float s1f = (vn1 - THR >= 0.f) ? 1.f : 0.f;
            float s2f = (vn2 - THR >= 0.f) ? 1.f : 0.f;
            float s3  = (vn3 - THR >= 0.f) ? 1.f : 0.f;
            *(float4*)&g_v2[idx] = make_float4(vn0, vn1, vn2, vn3);
            *(float4*)&g_a2[idx] = make_float4(rh2.x * aa.x + bb2.x * s0,
                                               rh2.y * aa.y + bb2.y * s1f,
                                               rh2.z * aa.z + bb2.z * s2f,
                                               rh2.w * aa.w + bb2.w * s3);
            *(float4*)&s2w[idx]  = make_float4(s0, s1f, s2f, s3);
        }
        grid_sync(++epoch);
    }

    if (bx >= 128 && bx < 144) {
        const float* __restrict__ s2r = g_s2[(T_ - 1) & 1];
        for (int q = 0; q < nro; ++q) {
            const float4* sv = (const float4*)&s2r[rb[q] * H2];
            const float4* wv = (const float4*)&W3[ro[q] * H2];
            float4 acc4 = make_float4(0.f, 0.f, 0.f, 0.f);
#pragma unroll 4
            for (int k = 0; k < H2 / 4; ++k) {
                float4 s4 = __ldcg(&sv[k]);
                float4 w4 = __ldg(&wv[k]);
                acc4.x += s4.x * w4.x; acc4.y += s4.y * w4.y;
                acc4.z += s4.z * w4.z; acc4.w += s4.w * w4.w;
            }
            float I3 = (acc4.x + acc4.y) + (acc4.z + acc4.w);
            vo[q] = rbo[q] * vo[q] + (1.f - rbo[q]) * I3;
            osum[q] += vo[q];
            out[rb[q] * O_ + ro[q]] = osum[q] * (1.0f / (float)T_);
        }
    }
}

// ---------------- launch ---------------------------------------------------
extern "C" void kernel_launch(void* const* d_in, const int* in_sizes, int n_in,
                              void* d_out, int out_size) {
    const float* x      = (const float*)d_in[0];
    const float* W1     = (const float*)d_in[1];
    const float* Wrec   = (const float*)d_in[2];
    const float* W2     = (const float*)d_in[3];
    const float* W3     = (const float*)d_in[4];
    const float* alpha1 = (const float*)d_in[5];
    const float* rho1   = (const float*)d_in[6];
    const float* ba1    = (const float*)d_in[7];
    const float* alpha2 = (const float*)d_in[8];
    const float* rho2   = (const float*)d_in[9];
    const float* ba2    = (const float*)d_in[10];
    const float* bout   = (const float*)d_in[11];
    float* out = (float*)d_out;

    cudaFuncSetAttribute(ff_mma_kernel,
                         cudaFuncAttributeMaxDynamicSharedMemorySize, 65536);

    init_kernel<<<1024, 256>>>();
    prep_kernel<<<2048, 256>>>(Wrec, W2);
    convert_kernel<<<2048, 256>>>(x, W1);
    ff_mma_kernel<<<dim3(8, 500), 256, 65536>>>();
    sweep_kernel<<<B_ * H1 / 256, 256>>>(alpha1, rho1, ba1);
    snn_kernel<<<NB, 256>>>(W3, alpha1, rho1, ba1, alpha2, rho2, ba2, bout, out);
}

// round 16
// speedup vs baseline: 45.6477x; 1.1020x over previous
#include <cuda_runtime.h>
#include <cuda_bf16.h>
#include <cstdint>

typedef unsigned long long ull;

#define B_  256
#define T_  250
#define C_  700
#define KP  704
#define H1  1024
#define H2  512
#define O_  35
#define NB  148
#define THR 1.0f
#define MROWS (T_ * B_)      // 64000
#define NCH 11               // 704 / 64 k-chunks

// ---------------- device scratch (no allocations allowed) ----------------
__device__ __nv_bfloat16 g_ffh[(size_t)MROWS * H1];    // [row][h1]  131MB
__device__ __nv_bfloat16 g_xbf[(size_t)MROWS * KP];    // [row][k]    90MB
__device__ __nv_bfloat16 g_w1bf[(size_t)H1 * KP];      // [h][k]      1.4MB
__device__ float g_WrecT[H1 * H1];
__device__ float g_W2T[H1 * H2];
__device__ float g_v1[B_ * H1], g_a1[B_ * H1];
__device__ float g_s1[2][B_ * H1];
__device__ float g_v2[B_ * H2], g_a2[B_ * H2];
__device__ float g_s2[2][B_ * H2];
__device__ unsigned g_cnt, g_gen;
__device__ unsigned g_flag;

// ---------------- f32x2 helpers (fallback path) ----------------------------
__device__ __forceinline__ ull pack2(float lo, float hi) {
    ull r; asm("mov.b64 %0, {%1, %2};" : "=l"(r) : "f"(lo), "f"(hi)); return r;
}
__device__ __forceinline__ void fma2(ull& d, ull a, ull b) {
    asm("fma.rn.f32x2 %0, %1, %2, %0;" : "+l"(d) : "l"(a), "l"(b));
}
__device__ __forceinline__ void unpack2(ull v, float& lo, float& hi) {
    asm("mov.b64 {%0, %1}, %2;" : "=f"(lo), "=f"(hi) : "l"(v));
}

__device__ __forceinline__ uint32_t smem_u32(const void* p) {
    uint32_t a;
    asm("{ .reg .u64 t; cvta.to.shared.u64 t, %1; cvt.u32.u64 %0, t; }"
        : "=r"(a) : "l"(p));
    return a;
}

// ---------------- software grid barrier (proven R9) ------------------------
__device__ __forceinline__ void grid_sync(unsigned e) {
    __syncthreads();
    __threadfence();
    if (threadIdx.x == 0) {
        unsigned prev = atomicAdd(&g_cnt, 1u);
        if (prev == NB - 1) {
            g_cnt = 0;
            __threadfence();
            atomicExch(&g_gen, e);
        } else {
            while (atomicAdd(&g_gen, 0u) < e) { __nanosleep(64); }
        }
    }
    __syncthreads();
    __threadfence();
}

// ---------------- init ------------------------------------------------------
__global__ void init_kernel() {
    int i = blockIdx.x * blockDim.x + threadIdx.x;
    int stride = gridDim.x * blockDim.x;
    if (i == 0) { g_cnt = 0; g_gen = 0; g_flag = 0; }
    for (int k = i; k < B_ * H1; k += stride) {
        g_v1[k] = 0.f; g_a1[k] = 0.f; g_s1[0][k] = 0.f; g_s1[1][k] = 0.f;
    }
    for (int k = i; k < B_ * H2; k += stride) {
        g_v2[k] = 0.f; g_a2[k] = 0.f; g_s2[0][k] = 0.f; g_s2[1][k] = 0.f;
    }
}

// ---------------- transpose weights (fallback path only) --------------------
__global__ void prep_kernel(const float* __restrict__ Wrec,
                            const float* __restrict__ W2) {
    int i = blockIdx.x * blockDim.x + threadIdx.x;
    int stride = gridDim.x * blockDim.x;
    for (int k = i; k < H1 * H1; k += stride) {
        int r = k / H1, j = k % H1;
        g_WrecT[k] = Wrec[j * H1 + r];
    }
    for (int k = i; k < H1 * H2; k += stride) {
        int r = k / H2, j = k % H2;
        g_W2T[k] = W2[j * H1 + r];
    }
}

// ---------------- convert x, W1 to bf16 (K padded to 704) -------------------
// block = 32 rows; thread (row, o): 22 float4 per (row-lane) covering 704 cols.
__global__ void __launch_bounds__(256) convert_kernel(
    const float* __restrict__ x, const float* __restrict__ W1) {
    const int bid = blockIdx.x;
    const int row = (bid < 2000 ? bid * 32 : (bid - 2000) * 32) + (threadIdx.x >> 3);
    const int o = threadIdx.x & 7;
    const float* src;
    __nv_bfloat16* dst;
    if (bid < 2000) {               // x rows
        int b = row & 255, t = row >> 8;
        src = &x[((size_t)b * T_ + t) * C_];
        dst = &g_xbf[(size_t)row * KP];
    } else {                        // W1 rows
        src = &W1[(size_t)row * C_];
        dst = &g_w1bf[(size_t)row * KP];
    }
#pragma unroll
    for (int j = 0; j < 22; ++j) {
        int c = (o + j * 8) * 4;
        float4 v = make_float4(0.f, 0.f, 0.f, 0.f);
        if (c < C_) v = *(const float4*)&src[c];
        __nv_bfloat162 lo = __float22bfloat162_rn(make_float2(v.x, v.y));
        __nv_bfloat162 hi = __float22bfloat162_rn(make_float2(v.z, v.w));
        ull pk; asm("mov.b64 %0, {%1, %2};" : "=l"(pk)
                    : "r"(*(uint32_t*)&lo), "r"(*(uint32_t*)&hi));
        *(ull*)&dst[c] = pk;
    }
}

// ---------------- FF GEMM via mma.sync bf16 (HMMA, sm_103-safe) -------------
// g_ffh[row][h] = bf16( sum_k xbf[row][k] * w1bf[h][k] )
// CTA tile 128M x 256N, k-chunks of 64 (128B rows, SW128), 3-stage cp.async,
// 8 warps (2M x 4N), warp tile 64x64.
__global__ void __launch_bounds__(256) ff_mma_kernel() {
    extern __shared__ __align__(1024) char dsm[];
    const int tid = threadIdx.x;
    const int wid = tid >> 5, lane = tid & 31;
    const int n0 = blockIdx.x * 256;
    const int row0 = blockIdx.y * 128;

    const uint32_t smem0 = smem_u32(dsm);
    uint32_t sA[3], sB[3];
#pragma unroll
    for (int s = 0; s < 3; ++s) { sA[s] = smem0 + s * 49152; sB[s] = sA[s] + 16384; }

    // ---- A loads: thread -> (row ar, half aq), 4 x 16B ----
    const int ar = tid & 127;
    const int aq = tid >> 7;
    const char* gA = (const char*)g_xbf + (size_t)(row0 + ar) * (KP * 2) + aq * 64;
    uint32_t aOff[4];
#pragma unroll
    for (int o = 0; o < 4; ++o) {
        uint32_t kb = aq * 64 + o * 16;
        aOff[o] = ar * 128 + (kb ^ ((ar & 7) << 4));
    }
    // ---- B loads: thread -> full row tid (0..255), 8 x 16B ----
    const char* gB = (const char*)g_w1bf + (size_t)(n0 + tid) * (KP * 2);
    uint32_t bOff[8];
#pragma unroll
    for (int o = 0; o < 8; ++o)
        bOff[o] = tid * 128 + ((o * 16) ^ ((tid & 7) << 4));

    // ---- compute mapping: 2M x 4N warps, warp tile 64x64 ----
    const int wm = wid & 1;
    const int wn = wid >> 1;
    float acc[4][8][4];
#pragma unroll
    for (int a = 0; a < 4; ++a)
#pragma unroll
        for (int b = 0; b < 8; ++b)
#pragma unroll
            for (int c = 0; c < 4; ++c) acc[a][b][c] = 0.f;

    int a_row[4], b_row[4];
#pragma unroll
    for (int mi = 0; mi < 4; ++mi)
        a_row[mi] = wm * 64 + mi * 16 + (lane & 15);
#pragma unroll
    for (int pj = 0; pj < 4; ++pj)
        b_row[pj] = wn * 64 + pj * 16 + ((lane >> 4) & 1) * 8 + (lane & 7);
    const uint32_t a_klane = ((lane >> 4) & 1) * 16;
    const uint32_t b_klane = ((lane >> 3) & 1) * 16;

#define ISSUE(ch, s) do {                                                        \
        const char* ga_ = gA + (ch) * 128;                                       \
        const char* gb_ = gB + (ch) * 128;                                       \
        _Pragma("unroll")                                                        \
        for (int o = 0; o < 4; ++o)                                              \
            asm volatile("cp.async.cg.shared.global [%0], [%1], 16;"             \
                         :: "r"(sA[s] + aOff[o]), "l"(ga_ + o * 16));            \
        _Pragma("unroll")                                                        \
        for (int o = 0; o < 8; ++o)                                              \
            asm volatile("cp.async.cg.shared.global [%0], [%1], 16;"             \
                         :: "r"(sB[s] + bOff[o]), "l"(gb_ + o * 16));            \
        asm volatile("cp.async.commit_group;" ::: "memory");                     \
    } while (0)

    ISSUE(0, 0);
    ISSUE(1, 1);

    for (int ch = 0; ch < NCH; ++ch) {
        const int s = ch % 3;
        if (ch < NCH - 1) asm volatile("cp.async.wait_group 1;" ::: "memory");
        else              asm volatile("cp.async.wait_group 0;" ::: "memory");
        __syncthreads();
        if (ch + 2 < NCH) ISSUE(ch + 2, (ch + 2) % 3);

#pragma unroll
        for (int ks = 0; ks < 4; ++ks) {
            const uint32_t kbase = ks * 32;
            uint32_t a[4][4], bf[8][2];
#pragma unroll
            for (int mi = 0; mi < 4; ++mi) {
                uint32_t addr = sA[s] + a_row[mi] * 128 +
                                ((kbase + a_klane) ^ ((a_row[mi] & 7) << 4));
                asm volatile(
                    "ldmatrix.sync.aligned.m8n8.x4.shared.b16 {%0,%1,%2,%3}, [%4];"
                    : "=r"(a[mi][0]), "=r"(a[mi][1]), "=r"(a[mi][2]), "=r"(a[mi][3])
                    : "r"(addr));
            }
#pragma unroll
            for (int pj = 0; pj < 4; ++pj) {
                uint32_t addr = sB[s] + b_row[pj] * 128 +
                                ((kbase + b_klane) ^ ((b_row[pj] & 7) << 4));
                uint32_t r0, r1, r2, r3;
                asm volatile(
                    "ldmatrix.sync.aligned.m8n8.x4.shared.b16 {%0,%1,%2,%3}, [%4];"
                    : "=r"(r0), "=r"(r1), "=r"(r2), "=r"(r3)
                    : "r"(addr));
                bf[pj * 2 + 0][0] = r0; bf[pj * 2 + 0][1] = r1;
                bf[pj * 2 + 1][0] = r2; bf[pj * 2 + 1][1] = r3;
            }
#pragma unroll
            for (int mi = 0; mi < 4; ++mi) {
#pragma unroll
                for (int nj = 0; nj < 8; ++nj) {
                    asm volatile(
                        "mma.sync.aligned.m16n8k16.row.col.f32.bf16.bf16.f32 "
                        "{%0,%1,%2,%3}, {%4,%5,%6,%7}, {%8,%9}, {%0,%1,%2,%3};"
                        : "+f"(acc[mi][nj][0]), "+f"(acc[mi][nj][1]),
                          "+f"(acc[mi][nj][2]), "+f"(acc[mi][nj][3])
                        : "r"(a[mi][0]), "r"(a[mi][1]), "r"(a[mi][2]), "r"(a[mi][3]),
                          "r"(bf[nj][0]), "r"(bf[nj][1]));
                }
            }
        }
    }

    // ---- epilogue: fragments -> bf16 g_ffh[row][h] ----
    const int g = lane >> 2, tig = lane & 3;
#pragma unroll
    for (int mi = 0; mi < 4; ++mi) {
        int baseRow = row0 + wm * 64 + mi * 16;
#pragma unroll
        for (int nj = 0; nj < 8; ++nj) {
            int col = n0 + wn * 64 + nj * 8 + tig * 2;
            __nv_bfloat162 lo = __float22bfloat162_rn(
                make_float2(acc[mi][nj][0], acc[mi][nj][1]));
            __nv_bfloat162 hi = __float22bfloat162_rn(
                make_float2(acc[mi][nj][2], acc[mi][nj][3]));
            *(uint32_t*)&g_ffh[(size_t)(baseRow + g) * H1 + col] = *(uint32_t*)&lo;
            *(uint32_t*)&g_ffh[(size_t)(baseRow + g + 8) * H1 + col] = *(uint32_t*)&hi;
        }
    }
#undef ISSUE
}

// ---------------- sweep: per-(b,h) layer-1 dynamics, detect any spike -------
__global__ void __launch_bounds__(256) sweep_kernel(
    const float* __restrict__ alpha1, const float* __restrict__ rho1,
    const float* __restrict__ ba1)
{
    int idx = blockIdx.x * blockDim.x + threadIdx.x;   // 0..B_*H1-1
    int h = idx & (H1 - 1);
    float al = alpha1[h], rh = rho1[h], bt = ba1[h];
    float v = 0.f, a = 0.f, s = 0.f;
    unsigned any = 0;
    const unsigned short* p = (const unsigned short*)&g_ffh[idx];
#pragma unroll 2
    for (int t = 0; t < T_; ++t) {
        unsigned short u = __ldcs(p);
        p += B_ * H1;
        float f = __bfloat162float(__ushort_as_bfloat16(u));
        float vn = al * (v - s * THR) + (1.f - al) * (f - a);
        s = (vn - THR >= 0.f) ? 1.f : 0.f;
        a = rh * a + bt * s;
        v = vn;
        any |= (s != 0.f);
    }
    if (any) atomicOr(&g_flag, 1u);
}

// ---------------- persistent SNN kernel (flag-gated fallback) ---------------
__global__ void __launch_bounds__(256, 1) snn_kernel(
    const float* __restrict__ W3,
    const float* __restrict__ alpha1, const float* __restrict__ rho1,
    const float* __restrict__ ba1,
    const float* __restrict__ alpha2, const float* __restrict__ rho2,
    const float* __restrict__ ba2,
    const float* __restrict__ beta_out,
    float* __restrict__ out)
{
    const int tid = threadIdx.x;
    const int bx = blockIdx.x;

    if (g_flag == 0u) {
        for (int i = bx * 256 + tid; i < B_ * O_; i += NB * 256) out[i] = 0.f;
        return;
    }

    __shared__ float As[32][34];
    __shared__ float Bs[32][68];
    unsigned epoch = 0;

    const int m0  = (bx >> 4) * 32;
    const int n0  = (bx & 15) * 64;
    const int n0b = (bx & 15) * 32;
    const int la_m = tid >> 3;
    const int la_k = (tid & 7) << 2;
    const int lb_r = tid >> 4;
    const int lb_c = (tid & 15) << 2;
    const int mb   = (tid >> 4) << 1;
    const int nb   = (tid & 15) << 2;
    const int arow = tid >> 3;
    const int nb2  = (tid & 7) << 2;

    float4 al1, rh1, bb1, al2, rh2, bb2;
    if (bx < 128) {
        al1 = *(const float4*)&alpha1[n0 + nb];
        rh1 = *(const float4*)&rho1[n0 + nb];
        bb1 = *(const float4*)&ba1[n0 + nb];
        al2 = *(const float4*)&alpha2[n0b + nb2];
        rh2 = *(const float4*)&rho2[n0b + nb2];
        bb2 = *(const float4*)&ba2[n0b + nb2];
    }
    int rb[3], ro[3]; float rbo[3]; int nro = 0;
    float vo[3] = {0.f,0.f,0.f}, osum[3] = {0.f,0.f,0.f};
    if (bx >= 128 && bx < 144) {
        int base = (bx - 128) * 256 + tid;
        for (int jj = base; jj < B_ * O_; jj += 4096) {
            rb[nro] = jj / O_;
            ro[nro] = jj % O_;
            rbo[nro] = beta_out[jj % O_];
            nro++;
        }
    }

    for (int t = 0; t < T_; ++t) {
        const int par = t & 1;
        const float* __restrict__ s1r = g_s1[par];
        float* __restrict__ s1w = g_s1[par ^ 1];

        if (bx < 128) {
            ull a00 = 0, a01 = 0, a10 = 0, a11 = 0;
            float4 av  = __ldcg((const float4*)&s1r[(size_t)(m0 + la_m) * H1 + la_k]);
            float4 b0v = __ldg((const float4*)&g_WrecT[(size_t)lb_r * H1 + n0 + lb_c]);
            float4 b1v = __ldg((const float4*)&g_WrecT[(size_t)(lb_r + 16) * H1 + n0 + lb_c]);
            for (int k0 = 0; k0 < H1; k0 += 32) {
                __syncthreads();
                As[la_k + 0][la_m] = av.x;
                As[la_k + 1][la_m] = av.y;
                As[la_k + 2][la_m] = av.z;
                As[la_k + 3][la_m] = av.w;
                *(float4*)&Bs[lb_r][lb_c] = b0v;
                *(float4*)&Bs[lb_r + 16][lb_c] = b1v;
                __syncthreads();
                if (k0 + 32 < H1) {
                    int kn = k0 + 32;
                    av  = __ldcg((const float4*)&s1r[(size_t)(m0 + la_m) * H1 + kn + la_k]);
                    b0v = __ldg((const float4*)&g_WrecT[(size_t)(kn + lb_r) * H1 + n0 + lb_c]);
                    b1v = __ldg((const float4*)&g_WrecT[(size_t)(kn + lb_r + 16) * H1 + n0 + lb_c]);
                }
#pragma unroll
                for (int k = 0; k < 32; ++k) {
                    ull ap = *(const ull*)&As[k][mb];
                    float x0, x1; unpack2(ap, x0, x1);
                    ull bp0 = *(const ull*)&Bs[k][nb];
                    ull bp1 = *(const ull*)&Bs[k][nb + 2];
                    ull s0 = pack2(x0, x0), s1x = pack2(x1, x1);
                    fma2(a00, s0, bp0);  fma2(a01, s0, bp1);
                    fma2(a10, s1x, bp0); fma2(a11, s1x, bp1);
                }
            }
            const size_t ffb = (size_t)t * B_ * H1;
#pragma unroll
            for (int r = 0; r < 2; ++r) {
                int b = m0 + mb + r;
                size_t idx = (size_t)b * H1 + n0 + nb;
                float i0, i1, i2, i3;
                unpack2(r ? a10 : a00, i0, i1);
                unpack2(r ? a11 : a01, i2, i3);
                const __nv_bfloat162* fp = (const __nv_bfloat162*)&g_ffh[ffb + idx];
                __nv_bfloat162 p01 = fp[0], p23 = fp[1];
                float f0 = __bfloat162float(__low2bfloat16(p01));
                float f1 = __bfloat162float(__high2bfloat16(p01));
                float f2 = __bfloat162float(__low2bfloat16(p23));
                float f3 = __bfloat162float(__high2bfloat16(p23));
                float4 spv = *(const float4*)&s1r[idx];
                float4 vv  = *(const float4*)&g_v1[idx];
                float4 aa  = *(const float4*)&g_a1[idx];
                float I0 = i0 + f0, I1 = i1 + f1, I2 = i2 + f2, I3 = i3 + f3;
                float vn0 = al1.x * (vv.x - spv.x * THR) + (1.f - al1.x) * (I0 - aa.x);
                float vn1 = al1.y * (vv.y - spv.y * THR) + (1.f - al1.y) * (I1 - aa.y);
                float vn2 = al1.z * (vv.z - spv.z * THR) + (1.f - al1.z) * (I2 - aa.z);
                float vn3 = al1.w * (vv.w - spv.w * THR) + (1.f - al1.w) * (I3 - aa.w);
                float s0  = (vn0 - THR >= 0.f) ? 1.f : 0.f;
                float s1f = (vn1 - THR >= 0.f) ? 1.f : 0.f;
                float s2f = (vn2 - THR >= 0.f) ? 1.f : 0.f;
                float s3  = (vn3 - THR >= 0.f) ? 1.f : 0.f;
                *(float4*)&g_v1[idx] = make_float4(vn0, vn1, vn2, vn3);
                *(float4*)&g_a1[idx] = make_float4(rh1.x * aa.x + bb1.x * s0,
                                                   rh1.y * aa.y + bb1.y * s1f,
                                                   rh1.z * aa.z + bb1.z * s2f,
                                                   rh1.w * aa.w + bb1.w * s3);
                *(float4*)&s1w[idx]  = make_float4(s0, s1f, s2f, s3);
            }
        } else if (bx < 144 && t > 0) {
            const float* __restrict__ s2r = g_s2[par ^ 1];
            for (int q = 0; q < nro; ++q) {
                const float4* sv = (const float4*)&s2r[rb[q] * H2];
                const float4* wv = (const float4*)&W3[ro[q] * H2];
                float4 acc4 = make_float4(0.f, 0.f, 0.f, 0.f);
#pragma unroll 4
                for (int k = 0; k < H2 / 4; ++k) {
                    float4 s4 = __ldcg(&sv[k]);
                    float4 w4 = __ldg(&wv[k]);
                    acc4.x += s4.x * w4.x; acc4.y += s4.y * w4.y;
                    acc4.z += s4.z * w4.z; acc4.w += s4.w * w4.w;
                }
                float I3 = (acc4.x + acc4.y) + (acc4.z + acc4.w);
                vo[q] = rbo[q] * vo[q] + (1.f - rbo[q]) * I3;
                osum[q] += vo[q];
            }
        }
        grid_sync(++epoch);

        if (bx < 128) {
            const float* __restrict__ s1c = s1w;
            ull c0 = 0, c1 = 0;
            float4 av = __ldcg((const float4*)&s1c[(size_t)(m0 + la_m) * H1 + la_k]);
            float4 bv = __ldg((const float4*)&g_W2T[(size_t)arow * H2 + n0b + nb2]);
            for (int k0 = 0; k0 < H1; k0 += 32) {
                __syncthreads();
                As[la_k + 0][la_m] = av.x;
                As[la_k + 1][la_m] = av.y;
                As[la_k + 2][la_m] = av.z;
                As[la_k + 3][la_m] = av.w;
                *(float4*)&Bs[arow][nb2] = bv;
                __syncthreads();
                if (k0 + 32 < H1) {
                    int kn = k0 + 32;
                    av = __ldcg((const float4*)&s1c[(size_t)(m0 + la_m) * H1 + kn + la_k]);
                    bv = __ldg((const float4*)&g_W2T[(size_t)(kn + arow) * H2 + n0b + nb2]);
                }
#pragma unroll
                for (int k = 0; k < 32; ++k) {
                    float a = As[k][arow];
                    ull asp = pack2(a, a);
                    fma2(c0, asp, *(const ull*)&Bs[k][nb2]);
                    fma2(c1, asp, *(const ull*)&Bs[k][nb2 + 2]);
                }
            }
            int b = m0 + arow;
            size_t idx = (size_t)b * H2 + n0b + nb2;
            float i0, i1, i2, i3;
            unpack2(c0, i0, i1);
            unpack2(c1, i2, i3);
            const float* __restrict__ s2p = g_s2[par ^ 1];
            float* __restrict__ s2w = g_s2[par];
            float4 spv = *(const float4*)&s2p[idx];
            float4 vv  = *(const float4*)&g_v2[idx];
            float4 aa  = *(const float4*)&g_a2[idx];
            float vn0 = al2.x * (vv.x - spv.x * THR) + (1.f - al2.x) * (i0 - aa.x);
            float vn1 = al2.y * (vv.y - spv.y * THR) + (1.f - al2.y) * (i1 - aa.y);
            float vn2 = al2.z * (vv.z - spv.z * THR) + (1.f - al2.z) * (i2 - aa.z);
            float vn3 = al2.w * (vv.w - spv.w * THR) + (1.f - al2.w) * (i3 - aa.w);
            float s0  = (vn0 - THR >= 0.f) ? 1.f : 0.f;
            float s1f = (vn1 - THR >= 0.f) ? 1.f : 0.f;
            float s2f = (vn2 - THR >= 0.f) ? 1.f : 0.f;
            float s3  = (vn3 - THR >= 0.f) ? 1.f : 0.f;
            *(float4*)&g_v2[idx] = make_float4(vn0, vn1, vn2, vn3);
            *(float4*)&g_a2[idx] = make_float4(rh2.x * aa.x + bb2.x * s0,
                                               rh2.y * aa.y + bb2.y * s1f,
                                               rh2.z * aa.z + bb2.z * s2f,
                                               rh2.w * aa.w + bb2.w * s3);
            *(float4*)&s2w[idx]  = make_float4(s0, s1f, s2f, s3);
        }
        grid_sync(++epoch);
    }

    if (bx >= 128 && bx < 144) {
        const float* __restrict__ s2r = g_s2[(T_ - 1) & 1];
        for (int q = 0; q < nro; ++q) {
            const float4* sv = (const float4*)&s2r[rb[q] * H2];
            const float4* wv = (const float4*)&W3[ro[q] * H2];
            float4 acc4 = make_float4(0.f, 0.f, 0.f, 0.f);
#pragma unroll 4
            for (int k = 0; k < H2 / 4; ++k) {
                float4 s4 = __ldcg(&sv[k]);
                float4 w4 = __ldg(&wv[k]);
                acc4.x += s4.x * w4.x; acc4.y += s4.y * w4.y;
                acc4.z += s4.z * w4.z; acc4.w += s4.w * w4.w;
            }
            float I3 = (acc4.x + acc4.y) + (acc4.z + acc4.w);
            vo[q] = rbo[q] * vo[q] + (1.f - rbo[q]) * I3;
            osum[q] += vo[q];
            out[rb[q] * O_ + ro[q]] = osum[q] * (1.0f / (float)T_);
        }
    }
}

// ---------------- launch ---------------------------------------------------
extern "C" void kernel_launch(void* const* d_in, const int* in_sizes, int n_in,
                              void* d_out, int out_size) {
    const float* x      = (const float*)d_in[0];
    const float* W1     = (const float*)d_in[1];
    const float* Wrec   = (const float*)d_in[2];
    const float* W2     = (const float*)d_in[3];
    const float* W3     = (const float*)d_in[4];
    const float* alpha1 = (const float*)d_in[5];
    const float* rho1   = (const float*)d_in[6];
    const float* ba1    = (const float*)d_in[7];
    const float* alpha2 = (const float*)d_in[8];
    const float* rho2   = (const float*)d_in[9];
    const float* ba2    = (const float*)d_in[10];
    const float* bout   = (const float*)d_in[11];
    float* out = (float*)d_out;

    cudaFuncSetAttribute(ff_mma_kernel,
                         cudaFuncAttributeMaxDynamicSharedMemorySize, 147456);

    init_kernel<<<1024, 256>>>();
    prep_kernel<<<2048, 256>>>(Wrec, W2);
    convert_kernel<<<2032, 256>>>(x, W1);     // 2000 x-blocks + 32 W1-blocks
    ff_mma_kernel<<<dim3(4, 500), 256, 147456>>>();
    sweep_kernel<<<B_ * H1 / 256, 256>>>(alpha1, rho1, ba1);
    snn_kernel<<<NB, 256>>>(W3, alpha1, rho1, ba1, alpha2, rho2, ba2, bout, out);
}

// round 17
// speedup vs baseline: 46.3256x; 1.0149x over previous
#include <cuda_runtime.h>
#include <cuda_bf16.h>
#include <cstdint>

typedef unsigned long long ull;

#define B_  256
#define T_  250
#define C_  700
#define KP  704
#define H1  1024
#define H2  512
#define O_  35
#define NB  148
#define THR 1.0f
#define MROWS (T_ * B_)      // 64000
#define NCH 11               // 704 / 64 k-chunks

// ---------------- device scratch (no allocations allowed) ----------------
__device__ __nv_bfloat16 g_ffh[(size_t)MROWS * H1];    // [row][h1]  131MB
__device__ __nv_bfloat16 g_xbf[(size_t)MROWS * KP];    // [row][k]    90MB
__device__ __nv_bfloat16 g_w1bf[(size_t)H1 * KP];      // [h][k]      1.4MB
__device__ float g_WrecT[H1 * H1];
__device__ float g_W2T[H1 * H2];
__device__ float g_v1[B_ * H1], g_a1[B_ * H1];
__device__ float g_s1[2][B_ * H1];
__device__ float g_v2[B_ * H2], g_a2[B_ * H2];
__device__ float g_s2[2][B_ * H2];
__device__ unsigned g_cnt, g_gen;
__device__ unsigned g_flag;

// ---------------- f32x2 helpers (fallback path) ----------------------------
__device__ __forceinline__ ull pack2(float lo, float hi) {
    ull r; asm("mov.b64 %0, {%1, %2};" : "=l"(r) : "f"(lo), "f"(hi)); return r;
}
__device__ __forceinline__ void fma2(ull& d, ull a, ull b) {
    asm("fma.rn.f32x2 %0, %1, %2, %0;" : "+l"(d) : "l"(a), "l"(b));
}
__device__ __forceinline__ void unpack2(ull v, float& lo, float& hi) {
    asm("mov.b64 {%0, %1}, %2;" : "=f"(lo), "=f"(hi) : "l"(v));
}

__device__ __forceinline__ uint32_t smem_u32(const void* p) {
    uint32_t a;
    asm("{ .reg .u64 t; cvta.to.shared.u64 t, %1; cvt.u32.u64 %0, t; }"
        : "=r"(a) : "l"(p));
    return a;
}

// ---------------- software grid barrier (proven R9) ------------------------
__device__ __forceinline__ void grid_sync(unsigned e) {
    __syncthreads();
    __threadfence();
    if (threadIdx.x == 0) {
        unsigned prev = atomicAdd(&g_cnt, 1u);
        if (prev == NB - 1) {
            g_cnt = 0;
            __threadfence();
            atomicExch(&g_gen, e);
        } else {
            while (atomicAdd(&g_gen, 0u) < e) { __nanosleep(64); }
        }
    }
    __syncthreads();
    __threadfence();
}

// ---------------- init ------------------------------------------------------
__global__ void init_kernel() {
    int i = blockIdx.x * blockDim.x + threadIdx.x;
    int stride = gridDim.x * blockDim.x;
    if (i == 0) { g_cnt = 0; g_gen = 0; g_flag = 0; }
    for (int k = i; k < B_ * H1; k += stride) {
        g_v1[k] = 0.f; g_a1[k] = 0.f; g_s1[0][k] = 0.f; g_s1[1][k] = 0.f;
    }
    for (int k = i; k < B_ * H2; k += stride) {
        g_v2[k] = 0.f; g_a2[k] = 0.f; g_s2[0][k] = 0.f; g_s2[1][k] = 0.f;
    }
}

// ---------------- transpose weights (fallback path only) --------------------
__global__ void prep_kernel(const float* __restrict__ Wrec,
                            const float* __restrict__ W2) {
    int i = blockIdx.x * blockDim.x + threadIdx.x;
    int stride = gridDim.x * blockDim.x;
    for (int k = i; k < H1 * H1; k += stride) {
        int r = k / H1, j = k % H1;
        g_WrecT[k] = Wrec[j * H1 + r];
    }
    for (int k = i; k < H1 * H2; k += stride) {
        int r = k / H2, j = k % H2;
        g_W2T[k] = W2[j * H1 + r];
    }
}

// ---------------- convert x, W1 to bf16 (K padded to 704) -------------------
__global__ void __launch_bounds__(256) convert_kernel(
    const float* __restrict__ x, const float* __restrict__ W1) {
    const int bid = blockIdx.x;
    const int row = (bid < 2000 ? bid * 32 : (bid - 2000) * 32) + (threadIdx.x >> 3);
    const int o = threadIdx.x & 7;
    const float* src;
    __nv_bfloat16* dst;
    if (bid < 2000) {               // x rows
        int b = row & 255, t = row >> 8;
        src = &x[((size_t)b * T_ + t) * C_];
        dst = &g_xbf[(size_t)row * KP];
    } else {                        // W1 rows
        src = &W1[(size_t)row * C_];
        dst = &g_w1bf[(size_t)row * KP];
    }
#pragma unroll
    for (int j = 0; j < 22; ++j) {
        int c = (o + j * 8) * 4;
        float4 v = make_float4(0.f, 0.f, 0.f, 0.f);
        if (c < C_) v = *(const float4*)&src[c];
        __nv_bfloat162 lo = __float22bfloat162_rn(make_float2(v.x, v.y));
        __nv_bfloat162 hi = __float22bfloat162_rn(make_float2(v.z, v.w));
        ull pk; asm("mov.b64 %0, {%1, %2};" : "=l"(pk)
                    : "r"(*(uint32_t*)&lo), "r"(*(uint32_t*)&hi));
        *(ull*)&dst[c] = pk;
    }
}

// ---------------- FF GEMM via mma.sync bf16 (HMMA, sm_103-safe) -------------
// g_ffh[row][h] = bf16( sum_k xbf[row][k] * w1bf[h][k] )
// CTA tile 128M x 128N, 4 warps (2M x 2N, warp tile 64x64), k-chunks of 64,
// 2-stage cp.async (64KB smem), target 3 CTAs/SM.
__global__ void __launch_bounds__(128, 3) ff_mma_kernel() {
    extern __shared__ __align__(1024) char dsm[];
    const int tid = threadIdx.x;
    const int wid = tid >> 5, lane = tid & 31;
    const int n0 = blockIdx.x * 128;
    const int row0 = blockIdx.y * 128;

    const uint32_t smem0 = smem_u32(dsm);
    uint32_t sA[2], sB[2];
#pragma unroll
    for (int s = 0; s < 2; ++s) { sA[s] = smem0 + s * 32768; sB[s] = sA[s] + 16384; }

    // ---- loads: thread -> full 128B row tid, 8 x 16B each for A and B ----
    const char* gA = (const char*)g_xbf + (size_t)(row0 + tid) * (KP * 2);
    const char* gB = (const char*)g_w1bf + (size_t)(n0 + tid) * (KP * 2);
    uint32_t rOff[8];
#pragma unroll
    for (int o = 0; o < 8; ++o)
        rOff[o] = tid * 128 + ((o * 16) ^ ((tid & 7) << 4));

    // ---- compute mapping: 2M x 2N warps, warp tile 64x64 ----
    const int wm = wid & 1;
    const int wn = wid >> 1;
    float acc[4][8][4];
#pragma unroll
    for (int a = 0; a < 4; ++a)
#pragma unroll
        for (int b = 0; b < 8; ++b)
#pragma unroll
            for (int c = 0; c < 4; ++c) acc[a][b][c] = 0.f;

    int a_row[4], b_row[4];
#pragma unroll
    for (int mi = 0; mi < 4; ++mi)
        a_row[mi] = wm * 64 + mi * 16 + (lane & 15);
#pragma unroll
    for (int pj = 0; pj < 4; ++pj)
        b_row[pj] = wn * 64 + pj * 16 + ((lane >> 4) & 1) * 8 + (lane & 7);
    const uint32_t a_klane = ((lane >> 4) & 1) * 16;
    const uint32_t b_klane = ((lane >> 3) & 1) * 16;

#define ISSUE(ch, s) do {                                                        \
        const char* ga_ = gA + (ch) * 128;                                       \
        const char* gb_ = gB + (ch) * 128;                                       \
        _Pragma("unroll")                                                        \
        for (int o = 0; o < 8; ++o) {                                            \
            asm volatile("cp.async.cg.shared.global [%0], [%1], 16;"             \
                         :: "r"(sA[s] + rOff[o]), "l"(ga_ + o * 16));            \
            asm volatile("cp.async.cg.shared.global [%0], [%1], 16;"             \
                         :: "r"(sB[s] + rOff[o]), "l"(gb_ + o * 16));            \
        }                                                                        \
        asm volatile("cp.async.commit_group;" ::: "memory");                     \
    } while (0)

    ISSUE(0, 0);

    for (int ch = 0; ch < NCH; ++ch) {
        const int p = ch & 1;
        asm volatile("cp.async.wait_group 0;" ::: "memory");
        __syncthreads();
        if (ch + 1 < NCH) ISSUE(ch + 1, 1 - p);

#pragma unroll
        for (int ks = 0; ks < 4; ++ks) {
            const uint32_t kbase = ks * 32;
            uint32_t a[4][4], bf[8][2];
#pragma unroll
            for (int mi = 0; mi < 4; ++mi) {
                uint32_t addr = sA[p] + a_row[mi] * 128 +
                                ((kbase + a_klane) ^ ((a_row[mi] & 7) << 4));
                asm volatile(
                    "ldmatrix.sync.aligned.m8n8.x4.shared.b16 {%0,%1,%2,%3}, [%4];"
                    : "=r"(a[mi][0]), "=r"(a[mi][1]), "=r"(a[mi][2]), "=r"(a[mi][3])
                    : "r"(addr));
            }
#pragma unroll
            for (int pj = 0; pj < 4; ++pj) {
                uint32_t addr = sB[p] + b_row[pj] * 128 +
                                ((kbase + b_klane) ^ ((b_row[pj] & 7) << 4));
                uint32_t r0, r1, r2, r3;
                asm volatile(
                    "ldmatrix.sync.aligned.m8n8.x4.shared.b16 {%0,%1,%2,%3}, [%4];"
                    : "=r"(r0), "=r"(r1), "=r"(r2), "=r"(r3)
                    : "r"(addr));
                bf[pj * 2 + 0][0] = r0; bf[pj * 2 + 0][1] = r1;
                bf[pj * 2 + 1][0] = r2; bf[pj * 2 + 1][1] = r3;
            }
#pragma unroll
            for (int mi = 0; mi < 4; ++mi) {
#pragma unroll
                for (int nj = 0; nj < 8; ++nj) {
                    asm volatile(
                        "mma.sync.aligned.m16n8k16.row.col.f32.bf16.bf16.f32 "
                        "{%0,%1,%2,%3}, {%4,%5,%6,%7}, {%8,%9}, {%0,%1,%2,%3};"
                        : "+f"(acc[mi][nj][0]), "+f"(acc[mi][nj][1]),
                          "+f"(acc[mi][nj][2]), "+f"(acc[mi][nj][3])
                        : "r"(a[mi][0]), "r"(a[mi][1]), "r"(a[mi][2]), "r"(a[mi][3]),
                          "r"(bf[nj][0]), "r"(bf[nj][1]));
                }
            }
        }
        __syncthreads();
    }

    // ---- epilogue: fragments -> bf16 g_ffh[row][h] ----
    const int g = lane >> 2, tig = lane & 3;
#pragma unroll
    for (int mi = 0; mi < 4; ++mi) {
        int baseRow = row0 + wm * 64 + mi * 16;
#pragma unroll
        for (int nj = 0; nj < 8; ++nj) {
            int col = n0 + wn * 64 + nj * 8 + tig * 2;
            __nv_bfloat162 lo = __float22bfloat162_rn(
                make_float2(acc[mi][nj][0], acc[mi][nj][1]));
            __nv_bfloat162 hi = __float22bfloat162_rn(
                make_float2(acc[mi][nj][2], acc[mi][nj][3]));
            *(uint32_t*)&g_ffh[(size_t)(baseRow + g) * H1 + col] = *(uint32_t*)&lo;
            *(uint32_t*)&g_ffh[(size_t)(baseRow + g + 8) * H1 + col] = *(uint32_t*)&hi;
        }
    }
#undef ISSUE
}

// ---------------- sweep: per-(b,h) layer-1 dynamics, detect any spike -------
__global__ void __launch_bounds__(256) sweep_kernel(
    const float* __restrict__ alpha1, const float* __restrict__ rho1,
    const float* __restrict__ ba1)
{
    int idx = blockIdx.x * blockDim.x + threadIdx.x;   // 0..B_*H1-1
    int h = idx & (H1 - 1);
    float al = alpha1[h], rh = rho1[h], bt = ba1[h];
    float v = 0.f, a = 0.f, s = 0.f;
    unsigned any = 0;
    const unsigned short* p = (const unsigned short*)&g_ffh[idx];
#pragma unroll 2
    for (int t = 0; t < T_; ++t) {
        unsigned short u = __ldcs(p);
        p += B_ * H1;
        float f = __bfloat162float(__ushort_as_bfloat16(u));
        float vn = al * (v - s * THR) + (1.f - al) * (f - a);
        s = (vn - THR >= 0.f) ? 1.f : 0.f;
        a = rh * a + bt * s;
        v = vn;
        any |= (s != 0.f);
    }
    if (any) atomicOr(&g_flag, 1u);
}

// ---------------- persistent SNN kernel (flag-gated fallback) ---------------
__global__ void __launch_bounds__(256, 1) snn_kernel(
    const float* __restrict__ W3,
    const float* __restrict__ alpha1, const float* __restrict__ rho1,
    const float* __restrict__ ba1,
    const float* __restrict__ alpha2, const float* __restrict__ rho2,
    const float* __restrict__ ba2,
    const float* __restrict__ beta_out,
    float* __restrict__ out)
{
    const int tid = threadIdx.x;
    const int bx = blockIdx.x;

    if (g_flag == 0u) {
        for (int i = bx * 256 + tid; i < B_ * O_; i += NB * 256) out[i] = 0.f;
        return;
    }

    __shared__ float As[32][34];
    __shared__ float Bs[32][68];
    unsigned epoch = 0;

    const int m0  = (bx >> 4) * 32;
    const int n0  = (bx & 15) * 64;
    const int n0b = (bx & 15) * 32;
    const int la_m = tid >> 3;
    const int la_k = (tid & 7) << 2;
    const int lb_r = tid >> 4;
    const int lb_c = (tid & 15) << 2;
    const int mb   = (tid >> 4) << 1;
    const int nb   = (tid & 15) << 2;
    const int arow = tid >> 3;
    const int nb2  = (tid & 7) << 2;

    float4 al1, rh1, bb1, al2, rh2, bb2;
    if (bx < 128) {
        al1 = *(const float4*)&alpha1[n0 + nb];
        rh1 = *(const float4*)&rho1[n0 + nb];
        bb1 = *(const float4*)&ba1[n0 + nb];
        al2 = *(const float4*)&alpha2[n0b + nb2];
        rh2 = *(const float4*)&rho2[n0b + nb2];
        bb2 = *(const float4*)&ba2[n0b + nb2];
    }
    int rb[3], ro[3]; float rbo[3]; int nro = 0;
    float vo[3] = {0.f,0.f,0.f}, osum[3] = {0.f,0.f,0.f};
    if (bx >= 128 && bx < 144) {
        int base = (bx - 128) * 256 + tid;
        for (int jj = base; jj < B_ * O_; jj += 4096) {
            rb[nro] = jj / O_;
            ro[nro] = jj % O_;
            rbo[nro] = beta_out[jj % O_];
            nro++;
        }
    }

    for (int t = 0; t < T_; ++t) {
        const int par = t & 1;
        const float* __restrict__ s1r = g_s1[par];
        float* __restrict__ s1w = g_s1[par ^ 1];

        if (bx < 128) {
            ull a00 = 0, a01 = 0, a10 = 0, a11 = 0;
            float4 av  = __ldcg((const float4*)&s1r[(size_t)(m0 + la_m) * H1 + la_k]);
            float4 b0v = __ldg((const float4*)&g_WrecT[(size_t)lb_r * H1 + n0 + lb_c]);
            float4 b1v = __ldg((const float4*)&g_WrecT[(size_t)(lb_r + 16) * H1 + n0 + lb_c]);
            for (int k0 = 0; k0 < H1; k0 += 32) {
                __syncthreads();
                As[la_k + 0][la_m] = av.x;
                As[la_k + 1][la_m] = av.y;
                As[la_k + 2][la_m] = av.z;
                As[la_k + 3][la_m] = av.w;
                *(float4*)&Bs[lb_r][lb_c] = b0v;
                *(float4*)&Bs[lb_r + 16][lb_c] = b1v;
                __syncthreads();
                if (k0 + 32 < H1) {
                    int kn = k0 + 32;
                    av  = __ldcg((const float4*)&s1r[(size_t)(m0 + la_m) * H1 + kn + la_k]);
                    b0v = __ldg((const float4*)&g_WrecT[(size_t)(kn + lb_r) * H1 + n0 + lb_c]);
                    b1v = __ldg((const float4*)&g_WrecT[(size_t)(kn + lb_r + 16) * H1 + n0 + lb_c]);
                }
#pragma unroll
                for (int k = 0; k < 32; ++k) {
                    ull ap = *(const ull*)&As[k][mb];
                    float x0, x1; unpack2(ap, x0, x1);
                    ull bp0 = *(const ull*)&Bs[k][nb];
                    ull bp1 = *(const ull*)&Bs[k][nb + 2];
                    ull s0 = pack2(x0, x0), s1x = pack2(x1, x1);
                    fma2(a00, s0, bp0);  fma2(a01, s0, bp1);
                    fma2(a10, s1x, bp0); fma2(a11, s1x, bp1);
                }
            }
            const size_t ffb = (size_t)t * B_ * H1;
#pragma unroll
            for (int r = 0; r < 2; ++r) {
                int b = m0 + mb + r;
                size_t idx = (size_t)b * H1 + n0 + nb;
                float i0, i1, i2, i3;
                unpack2(r ? a10 : a00, i0, i1);
                unpack2(r ? a11 : a01, i2, i3);
                const __nv_bfloat162* fp = (const __nv_bfloat162*)&g_ffh[ffb + idx];
                __nv_bfloat162 p01 = fp[0], p23 = fp[1];
                float f0 = __bfloat162float(__low2bfloat16(p01));
                float f1 = __bfloat162float(__high2bfloat16(p01));
                float f2 = __bfloat162float(__low2bfloat16(p23));
                float f3 = __bfloat162float(__high2bfloat16(p23));
                float4 spv = *(const float4*)&s1r[idx];
                float4 vv  = *(const float4*)&g_v1[idx];
                float4 aa  = *(const float4*)&g_a1[idx];
                float I0 = i0 + f0, I1 = i1 + f1, I2 = i2 + f2, I3 = i3 + f3;
                float vn0 = al1.x * (vv.x - spv.x * THR) + (1.f - al1.x) * (I0 - aa.x);
                float vn1 = al1.y * (vv.y - spv.y * THR) + (1.f - al1.y) * (I1 - aa.y);
                float vn2 = al1.z * (vv.z - spv.z * THR) + (1.f - al1.z) * (I2 - aa.z);
                float vn3 = al1.w * (vv.w - spv.w * THR) + (1.f - al1.w) * (I3 - aa.w);
                float s0  = (vn0 - THR >= 0.f) ? 1.f : 0.f;
                float s1f = (vn1 - THR >= 0.f) ? 1.f : 0.f;
                float s2f = (vn2 - THR >= 0.f) ? 1.f : 0.f;
                float s3  = (vn3 - THR >= 0.f) ? 1.f : 0.f;
                *(float4*)&g_v1[idx] = make_float4(vn0, vn1, vn2, vn3);
                *(float4*)&g_a1[idx] = make_float4(rh1.x * aa.x + bb1.x * s0,
                                                   rh1.y * aa.y + bb1.y * s1f,
                                                   rh1.z * aa.z + bb1.z * s2f,
                                                   rh1.w * aa.w + bb1.w * s3);
                *(float4*)&s1w[idx]  = make_float4(s0, s1f, s2f, s3);
            }
        } else if (bx < 144 && t > 0) {
            const float* __restrict__ s2r = g_s2[par ^ 1];
            for (int q = 0; q < nro; ++q) {
                const float4* sv = (const float4*)&s2r[rb[q] * H2];
                const float4* wv = (const float4*)&W3[ro[q] * H2];
                float4 acc4 = make_float4(0.f, 0.f, 0.f, 0.f);
#pragma unroll 4
                for (int k = 0; k < H2 / 4; ++k) {
                    float4 s4 = __ldcg(&sv[k]);
                    float4 w4 = __ldg(&wv[k]);
                    acc4.x += s4.x * w4.x; acc4.y += s4.y * w4.y;
                    acc4.z += s4.z * w4.z; acc4.w += s4.w * w4.w;
                }
                float I3 = (acc4.x + acc4.y) + (acc4.z + acc4.w);
                vo[q] = rbo[q] * vo[q] + (1.f - rbo[q]) * I3;
                osum[q] += vo[q];
            }
        }
        grid_sync(++epoch);

        if (bx < 128) {
            const float* __restrict__ s1c = s1w;
            ull c0 = 0, c1 = 0;
            float4 av = __ldcg((const float4*)&s1c[(size_t)(m0 + la_m) * H1 + la_k]);
            float4 bv = __ldg((const float4*)&g_W2T[(size_t)arow * H2 + n0b + nb2]);
            for (int k0 = 0; k0 < H1; k0 += 32) {
                __syncthreads();
                As[la_k + 0][la_m] = av.x;
                As[la_k + 1][la_m] = av.y;
                As[la_k + 2][la_m] = av.z;
                As[la_k + 3][la_m] = av.w;
                *(float4*)&Bs[arow][nb2] = bv;
                __syncthreads();
                if (k0 + 32 < H1) {
                    int kn = k0 + 32;
                    av = __ldcg((const float4*)&s1c[(size_t)(m0 + la_m) * H1 + kn + la_k]);
                    bv = __ldg((const float4*)&g_W2T[(size_t)(kn + arow) * H2 + n0b + nb2]);
                }
#pragma unroll
                for (int k = 0; k < 32; ++k) {
                    float a = As[k][arow];
                    ull asp = pack2(a, a);
                    fma2(c0, asp, *(const ull*)&Bs[k][nb2]);
                    fma2(c1, asp, *(const ull*)&Bs[k][nb2 + 2]);
                }
            }
            int b = m0 + arow;
            size_t idx = (size_t)b * H2 + n0b + nb2;
            float i0, i1, i2, i3;
            unpack2(c0, i0, i1);
            unpack2(c1, i2, i3);
            const float* __restrict__ s2p = g_s2[par ^ 1];
            float* __restrict__ s2w = g_s2[par];
            float4 spv = *(const float4*)&s2p[idx];
            float4 vv  = *(const float4*)&g_v2[idx];
            float4 aa  = *(const float4*)&g_a2[idx];
            float vn0 = al2.x * (vv.x - spv.x * THR) + (1.f - al2.x) * (i0 - aa.x);
            float vn1 = al2.y * (vv.y - spv.y * THR) + (1.f - al2.y) * (i1 - aa.y);
            float vn2 = al2.z * (vv.z - spv.z * THR) + (1.f - al2.z) * (i2 - aa.z);
            float vn3 = al2.w * (vv.w - spv.w * THR) + (1.f - al2.w) * (i3 - aa.w);
            float s0  = (vn0 - THR >= 0.f) ? 1.f : 0.f;
            float s1f = (vn1 - THR >= 0.f) ? 1.f : 0.f;
            float s2f = (vn2 - THR >= 0.f) ? 1.f : 0.f;
            float s3  = (vn3 - THR >= 0.f) ? 1.f : 0.f;
            *(float4*)&g_v2[idx] = make_float4(vn0, vn1, vn2, vn3);
            *(float4*)&g_a2[idx] = make_float4(rh2.x * aa.x + bb2.x * s0,
                                               rh2.y * aa.y + bb2.y * s1f,
                                               rh2.z * aa.z + bb2.z * s2f,
                                               rh2.w * aa.w + bb2.w * s3);
            *(float4*)&s2w[idx]  = make_float4(s0, s1f, s2f, s3);
        }
        grid_sync(++epoch);
    }

    if (bx >= 128 && bx < 144) {
        const float* __restrict__ s2r = g_s2[(T_ - 1) & 1];
        for (int q = 0; q < nro; ++q) {
            const float4* sv = (const float4*)&s2r[rb[q] * H2];
            const float4* wv = (const float4*)&W3[ro[q] * H2];
            float4 acc4 = make_float4(0.f, 0.f, 0.f, 0.f);
#pragma unroll 4
            for (int k = 0; k < H2 / 4; ++k) {
                float4 s4 = __ldcg(&sv[k]);
                float4 w4 = __ldg(&wv[k]);
                acc4.x += s4.x * w4.x; acc4.y += s4.y * w4.y;
                acc4.z += s4.z * w4.z; acc4.w += s4.w * w4.w;
            }
            float I3 = (acc4.x + acc4.y) + (acc4.z + acc4.w);
            vo[q] = rbo[q] * vo[q] + (1.f - rbo[q]) * I3;
            osum[q] += vo[q];
            out[rb[q] * O_ + ro[q]] = osum[q] * (1.0f / (float)T_);
        }
    }
}

// ---------------- launch ---------------------------------------------------
extern "C" void kernel_launch(void* const* d_in, const int* in_sizes, int n_in,
                              void* d_out, int out_size) {
    const float* x      = (const float*)d_in[0];
    const float* W1     = (const float*)d_in[1];
    const float* Wrec   = (const float*)d_in[2];
    const float* W2     = (const float*)d_in[3];
    const float* W3     = (const float*)d_in[4];
    const float* alpha1 = (const float*)d_in[5];
    const float* rho1   = (const float*)d_in[6];
    const float* ba1    = (const float*)d_in[7];
    const float* alpha2 = (const float*)d_in[8];
    const float* rho2   = (const float*)d_in[9];
    const float* ba2    = (const float*)d_in[10];
    const float* bout   = (const float*)d_in[11];
    float* out = (float*)d_out;

    cudaFuncSetAttribute(ff_mma_kernel,
                         cudaFuncAttributeMaxDynamicSharedMemorySize, 65536);

    init_kernel<<<1024, 256>>>();
    prep_kernel<<<2048, 256>>>(Wrec, W2);
    convert_kernel<<<2032, 256>>>(x, W1);     // 2000 x-blocks + 32 W1-blocks
    ff_mma_kernel<<<dim3(8, 500), 128, 65536>>>();
    sweep_kernel<<<B_ * H1 / 256, 256>>>(alpha1, rho1, ba1);
    snn_kernel<<<NB, 256>>>(W3, alpha1, rho1, ba1, alpha2, rho2, ba2, bout, out);
}